// round 13
// baseline (speedup 1.0000x reference)
#include <cuda_runtime.h>

// Problem constants
#define B_    2048
#define T_    512
#define FIN_  32
#define H_    64
#define G4_   256        // 4*H
#define HOR_  48
#define FOUT_ 8
#define NROW  7          // batch rows per CTA
#define NCTA  293        // ceil(2048/7)
#define RT    256
#define G0ROW (B_ * G4_)

typedef unsigned long long u64;

// ---------------- scratch (__device__ globals; no cudaMalloc allowed) ----------------
// d_g0 layout: [t][b][unit*4 + gate]  (float4 per hidden unit = {i,f,g,o})
__device__ float d_g0[(size_t)T_ * B_ * G4_];
__device__ float d_WcT[FIN_ * G4_];   // combined (Wih0 @ W_emb), pidx channel order
__device__ float d_bc[G4_];           // combined layer0 bias, pidx order
// woff-packed streamed weight matrices (L2-resident, shared by all CTAs)
__device__ float d_eWhh0[H_ * G4_];
__device__ float d_eWhh1[H_ * G4_];
__device__ float d_dWhh0[H_ * G4_];
__device__ float d_dWih0[H_ * G4_];
__device__ float d_dWhh1[H_ * G4_];

// ---------------- fast activations ----------------
__device__ __forceinline__ float sigf(float x) {
    return __fdividef(1.0f, 1.0f + __expf(-x));
}
__device__ __forceinline__ float tanh_f(float x) {
    return __fdividef(2.0f, 1.0f + __expf(-2.0f * x)) - 1.0f;
}
__device__ __forceinline__ void lstm4(float gi, float gf, float gg, float go,
                                      float& c, float* __restrict__ hout) {
    float cn = sigf(gf) * c + sigf(gi) * tanh_f(gg);
    c = cn;
    *hout = sigf(go) * tanh_f(cn);
}

// ---------------- packed fp32x2 helpers ----------------
__device__ __forceinline__ u64 fma2(u64 a, u64 b, u64 c) {
    u64 d;
    asm("fma.rn.f32x2 %0, %1, %2, %3;" : "=l"(d) : "l"(a), "l"(b), "l"(c));
    return d;
}
__device__ __forceinline__ float hadd2(u64 a) {
    float lo, hi;
    asm("mov.b64 {%0, %1}, %2;" : "=f"(lo), "=f"(hi) : "l"(a));
    return lo + hi;
}

// packed output-channel index: gate g (0..255) -> unit*4 + gate_slot (x-part layout)
__device__ __forceinline__ int pidx(int g) { return ((g & 63) << 2) + (g >> 6); }
// weight packing for W[g][k] of a 256x64 matrix:
// [ks(4)][kq(4)][gate_slot(4)][unit(64)][k&3]
__device__ __forceinline__ int woff(int g, int k) {
    return ((k >> 4) << 12) + (((k >> 2) & 3) << 10) + ((g >> 6) << 8)
         + ((g & 63) << 2) + (k & 3);
}

// ---------------- prep: combined weights / packed transposes ----------------
__global__ void prep_kernel(const float* __restrict__ W_emb, const float* __restrict__ b_emb,
                            const float* __restrict__ encWih, const float* __restrict__ encbih,
                            const float* __restrict__ encbhh, const float* __restrict__ encWhh,
                            const float* __restrict__ decWih, const float* __restrict__ decWhh)
{
    int g  = threadIdx.x;   // original gate index 0..255
    int bb = blockIdx.x;    // 0..32
    float wrow[H_];
#pragma unroll
    for (int h = 0; h < H_; h++) wrow[h] = encWih[g * H_ + h];

    if (bb == FIN_) {
        float b = encbih[g] + encbhh[g];
#pragma unroll
        for (int h = 0; h < H_; h++) b = fmaf(wrow[h], b_emb[h], b);
        d_bc[pidx(g)] = b;
#pragma unroll
        for (int k = 0; k < H_; k++) {
            int d = woff(g, k);
            d_eWhh0[d] = encWhh[g * H_ + k];
            d_eWhh1[d] = encWhh[16384 + g * H_ + k];
            d_dWhh0[d] = decWhh[g * H_ + k];
            d_dWih0[d] = decWih[g * H_ + k];
            d_dWhh1[d] = decWhh[16384 + g * H_ + k];
        }
    } else {
        int f = bb;
        float s = 0.f;
#pragma unroll
        for (int h = 0; h < H_; h++) s = fmaf(wrow[h], W_emb[h * FIN_ + f], s);
        d_WcT[f * G4_ + pidx(g)] = s;
    }
}

// ---------------- GEMM: d_g0[t][b][c] = X[b][t][:] @ WcT[:, c] + bc[c] ----------------
__global__ void __launch_bounds__(256)
emb_gemm(const float* __restrict__ X)
{
    __shared__ float sX[128 * FIN_];
    const int t   = blockIdx.y;
    const int b0  = blockIdx.x * 128;
    const int tid = threadIdx.x;   // packed channel

#pragma unroll
    for (int q = 0; q < 4; q++) {
        int lin = tid + q * 256;
        int rr = lin >> 3, f4 = lin & 7;
        float4 v = *(const float4*)(X + ((size_t)(b0 + rr) * T_ + t) * FIN_ + f4 * 4);
        *(float4*)(sX + rr * FIN_ + f4 * 4) = v;
    }
    float w[FIN_];
#pragma unroll
    for (int f = 0; f < FIN_; f++) w[f] = d_WcT[f * G4_ + tid];
    const float bias = d_bc[tid];
    __syncthreads();

    float* dst = d_g0 + (size_t)t * B_ * G4_ + (size_t)b0 * G4_ + tid;
#pragma unroll 2
    for (int rr = 0; rr < 128; rr++) {
        float a = bias;
        const float* xr = sX + rr * FIN_;
#pragma unroll
        for (int f = 0; f < FIN_; f += 4) {
            float4 x = *(const float4*)(xr + f);
            a = fmaf(x.x, w[f + 0], a);
            a = fmaf(x.y, w[f + 1], a);
            a = fmaf(x.z, w[f + 2], a);
            a = fmaf(x.w, w[f + 3], a);
        }
        dst[(size_t)rr * G4_] = a;
    }
}

// ---------------- matvec pieces ----------------
// smem matvec: 7 rows x 16 k x 4 gate-slots of unit gq
__device__ __forceinline__ void mv4(u64 acc[NROW][4], const float* __restrict__ hb,
                                    const float* __restrict__ wb, int gq)
{
#pragma unroll
    for (int kq = 0; kq < 4; kq++) {
        const float* wp = wb + kq * 1024 + (gq << 2);
        ulonglong2 wi = *(const ulonglong2*)(wp);
        ulonglong2 wf = *(const ulonglong2*)(wp + 256);
        ulonglong2 wg = *(const ulonglong2*)(wp + 512);
        ulonglong2 wo = *(const ulonglong2*)(wp + 768);
        const float* hq = hb + kq * 4;
#pragma unroll
        for (int r = 0; r < NROW; r++) {
            ulonglong2 h = *(const ulonglong2*)(hq + r * 64);
            acc[r][0] = fma2(h.x, wi.x, acc[r][0]);
            acc[r][1] = fma2(h.x, wf.x, acc[r][1]);
            acc[r][2] = fma2(h.x, wg.x, acc[r][2]);
            acc[r][3] = fma2(h.x, wo.x, acc[r][3]);
            acc[r][0] = fma2(h.y, wi.y, acc[r][0]);
            acc[r][1] = fma2(h.y, wf.y, acc[r][1]);
            acc[r][2] = fma2(h.y, wg.y, acc[r][2]);
            acc[r][3] = fma2(h.y, wo.y, acc[r][3]);
        }
    }
}

// preload kq=0 weight set of a streamed matrix (call EARLY to hide L2 latency)
__device__ __forceinline__ void preW(ulonglong2 pre[4], const float* __restrict__ gWks, int gq)
{
#pragma unroll
    for (int s = 0; s < 4; s++)
        pre[s] = __ldg((const ulonglong2*)(gWks + s * 256 + (gq << 2)));
}

// streamed matvec: weights from gmem (L2), kq=0 set supplied in pre[]
__device__ __forceinline__ void mv4s(u64 acc[NROW][4], const float* __restrict__ hb,
                                     const float* __restrict__ gWks, int gq,
                                     ulonglong2 pre[4])
{
#pragma unroll
    for (int kq = 0; kq < 4; kq++) {
        ulonglong2 nxt[4];
        if (kq < 3) {
#pragma unroll
            for (int s = 0; s < 4; s++)
                nxt[s] = __ldg((const ulonglong2*)(gWks + (kq + 1) * 1024 + s * 256 + (gq << 2)));
        }
        const float* hq = hb + kq * 4;
#pragma unroll
        for (int r = 0; r < NROW; r++) {
            ulonglong2 h = *(const ulonglong2*)(hq + r * 64);
            acc[r][0] = fma2(h.x, pre[0].x, acc[r][0]);
            acc[r][1] = fma2(h.x, pre[1].x, acc[r][1]);
            acc[r][2] = fma2(h.x, pre[2].x, acc[r][2]);
            acc[r][3] = fma2(h.x, pre[3].x, acc[r][3]);
            acc[r][0] = fma2(h.y, pre[0].y, acc[r][0]);
            acc[r][1] = fma2(h.y, pre[1].y, acc[r][1]);
            acc[r][2] = fma2(h.y, pre[2].y, acc[r][2]);
            acc[r][3] = fma2(h.y, pre[3].y, acc[r][3]);
        }
#pragma unroll
        for (int s = 0; s < 4; s++) pre[s] = nxt[s];
    }
}

__device__ __forceinline__ void store_p(const u64 acc[NROW][4], float* __restrict__ buf, int gq)
{
#pragma unroll
    for (int r = 0; r < NROW; r++) {
        float4 v;
        v.x = hadd2(acc[r][0]); v.y = hadd2(acc[r][1]);
        v.z = hadd2(acc[r][2]); v.w = hadd2(acc[r][3]);
        *(float4*)(buf + r * G4_ + (gq << 2)) = v;
    }
}

__device__ __forceinline__ void add_p(const u64 acc[NROW][4], float* __restrict__ buf, int gq)
{
#pragma unroll
    for (int r = 0; r < NROW; r++) {
        float* p = buf + r * G4_ + (gq << 2);
        float4 v = *(const float4*)(p);
        v.x += hadd2(acc[r][0]); v.y += hadd2(acc[r][1]);
        v.z += hadd2(acc[r][2]); v.w += hadd2(acc[r][3]);
        *(float4*)(p) = v;
    }
}

__device__ __forceinline__ float4 sum3(float4 a, float4 b, float4 d)
{
    float4 v;
    v.x = a.x + b.x + d.x; v.y = a.y + b.y + d.y;
    v.z = a.z + b.z + d.z; v.w = a.w + b.w + d.w;
    return v;
}

// smem per CTA: sW 16384 | sH 896 | sP0 1792 | sP1 1792 = 20864 floats = 83456 B
#define SMEM_FLOATS (16384 + 896 + 1792 + 1792)
#define SMEM_BYTES  (SMEM_FLOATS * 4)

__global__ void __launch_bounds__(RT, 2)
rnn_kernel(const float* __restrict__ encWih, const float* __restrict__ encWhh,
           const float* __restrict__ encbih, const float* __restrict__ encbhh,
           const float* __restrict__ decWih, const float* __restrict__ decWhh,
           const float* __restrict__ decbih, const float* __restrict__ decbhh,
           const float* __restrict__ Wreg,   const float* __restrict__ breg,
           float* __restrict__ out)
{
    extern __shared__ float sm[];
    float* sW  = sm;            // one matrix, woff layout (encoder: Wih1; decoder: dWih1)
    float* sH  = sm + 16384;    // h0 [7][64], h1 @ +448
    float* sP0 = sm + 17280;    // partial gate buffer A [7][256]
    float* sP1 = sm + 19072;    // partial gate buffer B [7][256]

    const int tid = threadIdx.x;
    const int gq  = tid & 63;          // hidden unit
    const int ks  = tid >> 6;          // k-split (k in [16ks, 16ks+16))
    const int b0  = blockIdx.x * NROW;

    float* myBuf = (ks < 2) ? sP0 : sP1;
    const bool addL0 = ((ks & 1) == 0);   // L0: even ks adds; odd stores. L1: swapped.

    // pack encoder Wih1 into smem
    for (int i = tid; i < 16384; i += RT) {
        int g = i >> 6, k = i & 63;
        sW[woff(g, k)] = encWih[16384 + i];
    }
    for (int i = tid; i < 896; i += RT) sH[i] = 0.f;

    // update-cell mapping: cell A = tid (rows 0..3), cell B = tid+256 (rows 4..6, tid<192)
    const int r0 = tid >> 6, u0 = tid & 63;
    const bool hasB = (tid < 192);
    const int r1 = (tid + 256) >> 6, u1 = (tid + 256) & 63;
    const int eoff0 = r0 * G4_ + (u0 << 2);
    const int eoff1 = r1 * G4_ + (u1 << 2);
    float* h0p0 = sH + r0 * 64 + u0;
    float* h0p1 = sH + r1 * 64 + u1;
    float* h1p0 = h0p0 + 448;
    float* h1p1 = h0p1 + 448;

    // encoder L1 biases for cells
    float4 eb1A, eb1B;
    eb1A.x = encbih[256 + u0] + encbhh[256 + u0];
    eb1A.y = encbih[320 + u0] + encbhh[320 + u0];
    eb1A.z = encbih[384 + u0] + encbhh[384 + u0];
    eb1A.w = encbih[448 + u0] + encbhh[448 + u0];
    eb1B.x = encbih[256 + u1] + encbhh[256 + u1];
    eb1B.y = encbih[320 + u1] + encbhh[320 + u1];
    eb1B.z = encbih[384 + u1] + encbhh[384 + u1];
    eb1B.w = encbih[448 + u1] + encbhh[448 + u1];

    // x-part gmem offsets for the cells (clamped for tail CTA)
    int bA = b0 + r0; if (bA >= B_) bA = B_ - 1;
    int bB = b0 + r1; if (bB >= B_) bB = B_ - 1;
    const size_t gxoA = (size_t)bA * G4_ + (u0 << 2);
    const size_t gxoB = (size_t)bB * G4_ + (u1 << 2);
    float4 gxA = *(const float4*)(d_g0 + gxoA);
    float4 gxB = hasB ? *(const float4*)(d_g0 + gxoB) : make_float4(0.f, 0.f, 0.f, 0.f);

    const float* hb0 = sH + ks * 16;
    const float* hb1 = hb0 + 448;
    float c0A = 0.f, c1A = 0.f, c0B = 0.f, c1B = 0.f;

    const float* gW0 = d_eWhh0 + ks * 4096;   // streamed matrices, this k-split
    const float* gW1 = d_eWhh1 + ks * 4096;
    ulonglong2 p0[4], p1[4];
    preW(p0, gW0, gq);          // hoisted: Whh0 kq=0 set for step 0
    __syncthreads();

    // -------------------- encoder: 512 steps --------------------
    for (int t = 0; t < T_; t++) {
        u64 acc[NROW][4];
        // ---- L0: Whh0 (streamed) x h0 ----
#pragma unroll
        for (int r = 0; r < NROW; r++) { acc[r][0] = acc[r][1] = acc[r][2] = acc[r][3] = 0ull; }
        mv4s(acc, hb0, gW0, gq, p0);
        preW(p1, gW1, gq);                     // hoist Whh1 kq=0 for L1
        if (!addL0) store_p(acc, myBuf, gq);
        __syncthreads();
        if (addL0) add_p(acc, myBuf, gq);
        __syncthreads();
        // ---- U0: gates = sP0 + sP1 + x-part ----
        {
            float4 p = *(const float4*)(sP0 + eoff0);
            float4 q = *(const float4*)(sP1 + eoff0);
            float4 v = sum3(p, q, gxA);
            lstm4(v.x, v.y, v.z, v.w, c0A, h0p0);
        }
        if (hasB) {
            float4 p = *(const float4*)(sP0 + eoff1);
            float4 q = *(const float4*)(sP1 + eoff1);
            float4 v = sum3(p, q, gxB);
            lstm4(v.x, v.y, v.z, v.w, c0B, h0p1);
        }
        if (t + 1 < T_) {                      // prefetch next x-part
            gxA = *(const float4*)(d_g0 + (size_t)(t + 1) * G0ROW + gxoA);
            if (hasB) gxB = *(const float4*)(d_g0 + (size_t)(t + 1) * G0ROW + gxoB);
        }
        __syncthreads();
        // ---- L1: Wih1 (smem) x h0_new + Whh1 (streamed) x h1 ----
#pragma unroll
        for (int r = 0; r < NROW; r++) { acc[r][0] = acc[r][1] = acc[r][2] = acc[r][3] = 0ull; }
        mv4(acc, hb0, sW + ks * 4096, gq);
        mv4s(acc, hb1, gW1, gq, p1);
        if (t + 1 < T_) preW(p0, gW0, gq);     // hoist Whh0 kq=0 for next step
        if (addL0) store_p(acc, myBuf, gq);    // roles swapped
        __syncthreads();
        if (!addL0) add_p(acc, myBuf, gq);
        __syncthreads();
        // ---- U1: gates = sP0 + sP1 + bias ----
        {
            float4 p = *(const float4*)(sP0 + eoff0);
            float4 q = *(const float4*)(sP1 + eoff0);
            float4 v = sum3(p, q, eb1A);
            lstm4(v.x, v.y, v.z, v.w, c1A, h1p0);
        }
        if (hasB) {
            float4 p = *(const float4*)(sP0 + eoff1);
            float4 q = *(const float4*)(sP1 + eoff1);
            float4 v = sum3(p, q, eb1B);
            lstm4(v.x, v.y, v.z, v.w, c1B, h1p1);
        }
        __syncthreads();
    }

    // -------------------- decoder setup --------------------
    for (int i = tid; i < 16384; i += RT) {
        int g = i >> 6, k = i & 63;
        sW[woff(g, k)] = decWih[16384 + i];    // dWih1 -> smem
    }
    float4 db0A, db0B, db1A, db1B;
    db0A.x = decbih[u0]       + decbhh[u0];
    db0A.y = decbih[64 + u0]  + decbhh[64 + u0];
    db0A.z = decbih[128 + u0] + decbhh[128 + u0];
    db0A.w = decbih[192 + u0] + decbhh[192 + u0];
    db0B.x = decbih[u1]       + decbhh[u1];
    db0B.y = decbih[64 + u1]  + decbhh[64 + u1];
    db0B.z = decbih[128 + u1] + decbhh[128 + u1];
    db0B.w = decbih[192 + u1] + decbhh[192 + u1];
    db1A.x = decbih[256 + u0] + decbhh[256 + u0];
    db1A.y = decbih[320 + u0] + decbhh[320 + u0];
    db1A.z = decbih[384 + u0] + decbhh[384 + u0];
    db1A.w = decbih[448 + u0] + decbhh[448 + u0];
    db1B.x = decbih[256 + u1] + decbhh[256 + u1];
    db1B.y = decbih[320 + u1] + decbhh[320 + u1];
    db1B.z = decbih[384 + u1] + decbhh[384 + u1];
    db1B.w = decbih[448 + u1] + decbhh[448 + u1];
    c0A = c1A = c0B = c1B = 0.f;               // c reset; h carries over
    const float* gD0 = d_dWhh0 + ks * 4096;
    const float* gD1 = d_dWih0 + ks * 4096;
    const float* gD2 = d_dWhh1 + ks * 4096;
    preW(p0, gD0, gq);
    __syncthreads();

    // -------------------- decoder: 48 steps --------------------
    for (int t = 0; t < HOR_; t++) {
        u64 acc[NROW][4];
        // ---- L0: dWhh0 (streamed) x h0 + dWih0 (streamed) x h1 ----
#pragma unroll
        for (int r = 0; r < NROW; r++) { acc[r][0] = acc[r][1] = acc[r][2] = acc[r][3] = 0ull; }
        mv4s(acc, hb0, gD0, gq, p0);
        preW(p1, gD1, gq);
        mv4s(acc, hb1, gD1, gq, p1);
        preW(p1, gD2, gq);                     // hoist dWhh1 for L1
        if (!addL0) store_p(acc, myBuf, gq);
        __syncthreads();
        if (addL0) add_p(acc, myBuf, gq);
        __syncthreads();
        {
            float4 p = *(const float4*)(sP0 + eoff0);
            float4 q = *(const float4*)(sP1 + eoff0);
            float4 v = sum3(p, q, db0A);
            lstm4(v.x, v.y, v.z, v.w, c0A, h0p0);
        }
        if (hasB) {
            float4 p = *(const float4*)(sP0 + eoff1);
            float4 q = *(const float4*)(sP1 + eoff1);
            float4 v = sum3(p, q, db0B);
            lstm4(v.x, v.y, v.z, v.w, c0B, h0p1);
        }
        __syncthreads();
        // ---- L1: dWih1 (smem) x h0 + dWhh1 (streamed) x h1 ----
#pragma unroll
        for (int r = 0; r < NROW; r++) { acc[r][0] = acc[r][1] = acc[r][2] = acc[r][3] = 0ull; }
        mv4(acc, hb0, sW + ks * 4096, gq);
        mv4s(acc, hb1, gD2, gq, p1);
        if (t + 1 < HOR_) preW(p0, gD0, gq);
        if (addL0) store_p(acc, myBuf, gq);
        __syncthreads();
        if (!addL0) add_p(acc, myBuf, gq);
        __syncthreads();
        {
            float4 p = *(const float4*)(sP0 + eoff0);
            float4 q = *(const float4*)(sP1 + eoff0);
            float4 v = sum3(p, q, db1A);
            lstm4(v.x, v.y, v.z, v.w, c1A, h1p0);
        }
        if (hasB) {
            float4 p = *(const float4*)(sP0 + eoff1);
            float4 q = *(const float4*)(sP1 + eoff1);
            float4 v = sum3(p, q, db1B);
            lstm4(v.x, v.y, v.z, v.w, c1B, h1p1);
        }
        __syncthreads();
        // ---- regression head ----
        if (tid < NROW * FOUT_) {
            int r = tid >> 3, o = tid & 7;
            int b = b0 + r;
            if (b < B_) {
                float a = __ldg(&breg[o]);
                const float* hr = sH + 448 + r * 64;
#pragma unroll
                for (int k = 0; k < H_; k += 4) {
                    float4 h4 = *(const float4*)(hr + k);
                    float4 w4 = __ldg((const float4*)(Wreg + o * H_ + k));
                    a = fmaf(h4.x, w4.x, a);
                    a = fmaf(h4.y, w4.y, a);
                    a = fmaf(h4.z, w4.z, a);
                    a = fmaf(h4.w, w4.w, a);
                }
                out[((size_t)b * HOR_ + t) * FOUT_ + o] = a;
            }
        }
    }
}

// ---------------- launch ----------------
extern "C" void kernel_launch(void* const* d_in, const int* in_sizes, int n_in,
                              void* d_out, int out_size)
{
    const float* X      = (const float*)d_in[0];
    // d_in[1] = X_mask : all-ones, unused by reference
    const float* W_emb  = (const float*)d_in[2];
    const float* b_emb  = (const float*)d_in[3];
    const float* encWih = (const float*)d_in[4];
    const float* encWhh = (const float*)d_in[5];
    const float* encbih = (const float*)d_in[6];
    const float* encbhh = (const float*)d_in[7];
    const float* decWih = (const float*)d_in[8];
    const float* decWhh = (const float*)d_in[9];
    const float* decbih = (const float*)d_in[10];
    const float* decbhh = (const float*)d_in[11];
    const float* W_reg  = (const float*)d_in[12];
    const float* b_reg  = (const float*)d_in[13];
    float* out = (float*)d_out;

    cudaFuncSetAttribute(rnn_kernel, cudaFuncAttributeMaxDynamicSharedMemorySize, SMEM_BYTES);

    prep_kernel<<<FIN_ + 1, 256>>>(W_emb, b_emb, encWih, encbih, encbhh, encWhh,
                                   decWih, decWhh);
    emb_gemm<<<dim3(B_ / 128, T_), 256>>>(X);
    rnn_kernel<<<NCTA, RT, SMEM_BYTES>>>(encWih, encWhh, encbih, encbhh,
                                         decWih, decWhh, decbih, decbhh,
                                         W_reg, b_reg, out);
}

// round 14
// speedup vs baseline: 1.2253x; 1.2253x over previous
#include <cuda_runtime.h>

// Problem constants
#define B_    2048
#define T_    512
#define FIN_  32
#define H_    64
#define G4_   256        // 4*H
#define HOR_  48
#define FOUT_ 8
#define NROW  14         // batch rows per CTA
#define NCTA  147        // ceil(2048/14)
#define RT    512
#define G0ROW (B_ * G4_)

typedef unsigned long long u64;

// ---------------- scratch (__device__ globals; no cudaMalloc allowed) ----------------
// d_g0 layout: [t][b][unit*4 + gate]  (float4 per hidden unit = {i,f,g,o})
__device__ float d_g0[(size_t)T_ * B_ * G4_];
__device__ float d_WcT[FIN_ * G4_];   // combined (Wih0 @ W_emb), pidx channel order
__device__ float d_bc[G4_];           // combined layer0 bias, pidx order
__device__ float d_wih0P[H_ * G4_];   // decoder Wih[0], off2-packed (L2-streamed in decoder)

// ---------------- fast activations ----------------
__device__ __forceinline__ float sigf(float x) {
    return __fdividef(1.0f, 1.0f + __expf(-x));
}
__device__ __forceinline__ float tanh_f(float x) {
    return __fdividef(2.0f, 1.0f + __expf(-2.0f * x)) - 1.0f;
}
__device__ __forceinline__ void lstm4(float gi, float gf, float gg, float go,
                                      float& c, float* __restrict__ hout) {
    float cn = sigf(gf) * c + sigf(gi) * tanh_f(gg);
    c = cn;
    *hout = sigf(go) * tanh_f(cn);
}

// ---------------- packed fp32x2 helpers ----------------
__device__ __forceinline__ u64 fma2(u64 a, u64 b, u64 c) {
    u64 d;
    asm("fma.rn.f32x2 %0, %1, %2, %3;" : "=l"(d) : "l"(a), "l"(b), "l"(c));
    return d;
}
__device__ __forceinline__ float hadd2(u64 a) {
    float lo, hi;
    asm("mov.b64 {%0, %1}, %2;" : "=f"(lo), "=f"(hi) : "l"(a));
    return lo + hi;
}

// per-row-half named barrier: rh 0 -> id 1 (warps 0-7), rh 1 -> id 2 (warps 8-15)
__device__ __forceinline__ void barh(int rh) {
    asm volatile("bar.sync %0, 256;" :: "r"(rh + 1) : "memory");
}

// packed output-channel index: gate g (0..255) -> unit*4 + gate_slot (x-part layout)
__device__ __forceinline__ int pidx(int g) { return ((g & 63) << 2) + (g >> 6); }
// weight packing W[g][k] -> [(k>>2)][g][k&3]  (one float4 = 4 consecutive k for gate g)
__device__ __forceinline__ int off2(int g, int k) {
    return ((k >> 2) << 10) + (g << 2) + (k & 3);
}

// ---------------- prep: combined weights / packed transposes ----------------
__global__ void prep_kernel(const float* __restrict__ W_emb, const float* __restrict__ b_emb,
                            const float* __restrict__ encWih, const float* __restrict__ encbih,
                            const float* __restrict__ encbhh, const float* __restrict__ decWih)
{
    int g  = threadIdx.x;   // original gate index 0..255
    int bb = blockIdx.x;    // 0..32
    float wrow[H_];
#pragma unroll
    for (int h = 0; h < H_; h++) wrow[h] = encWih[g * H_ + h];

    if (bb == FIN_) {
        float b = encbih[g] + encbhh[g];
#pragma unroll
        for (int h = 0; h < H_; h++) b = fmaf(wrow[h], b_emb[h], b);
        d_bc[pidx(g)] = b;
#pragma unroll
        for (int k = 0; k < H_; k++)
            d_wih0P[off2(g, k)] = decWih[g * H_ + k];
    } else {
        int f = bb;
        float s = 0.f;
#pragma unroll
        for (int h = 0; h < H_; h++) s = fmaf(wrow[h], W_emb[h * FIN_ + f], s);
        d_WcT[f * G4_ + pidx(g)] = s;
    }
}

// ---------------- GEMM: d_g0[t][b][c] = X[b][t][:] @ WcT[:, c] + bc[c] ----------------
__global__ void __launch_bounds__(256)
emb_gemm(const float* __restrict__ X)
{
    __shared__ float sX[128 * FIN_];
    const int t   = blockIdx.y;
    const int b0  = blockIdx.x * 128;
    const int tid = threadIdx.x;   // packed channel

#pragma unroll
    for (int q = 0; q < 4; q++) {
        int lin = tid + q * 256;
        int rr = lin >> 3, f4 = lin & 7;
        float4 v = *(const float4*)(X + ((size_t)(b0 + rr) * T_ + t) * FIN_ + f4 * 4);
        *(float4*)(sX + rr * FIN_ + f4 * 4) = v;
    }
    float w[FIN_];
#pragma unroll
    for (int f = 0; f < FIN_; f++) w[f] = d_WcT[f * G4_ + tid];
    const float bias = d_bc[tid];
    __syncthreads();

    float* dst = d_g0 + (size_t)t * B_ * G4_ + (size_t)b0 * G4_ + tid;
#pragma unroll 2
    for (int rr = 0; rr < 128; rr++) {
        float a = bias;
        const float* xr = sX + rr * FIN_;
#pragma unroll
        for (int f = 0; f < FIN_; f += 4) {
            float4 x = *(const float4*)(xr + f);
            a = fmaf(x.x, w[f + 0], a);
            a = fmaf(x.y, w[f + 1], a);
            a = fmaf(x.z, w[f + 2], a);
            a = fmaf(x.w, w[f + 3], a);
        }
        dst[(size_t)rr * G4_] = a;
    }
}

// smem: sW 3*16384 | sH 2*896 | qL1 3584 | qL0 3584 = 58112 floats = 232448 B (max)
#define SMEM_FLOATS (3*16384 + 2*896 + 3584 + 3584)
#define SMEM_BYTES  (SMEM_FLOATS * 4)

__global__ void __launch_bounds__(RT, 1)
rnn_kernel(const float* __restrict__ encWih, const float* __restrict__ encWhh,
           const float* __restrict__ encbih, const float* __restrict__ encbhh,
           const float* __restrict__ decWih, const float* __restrict__ decWhh,
           const float* __restrict__ decbih, const float* __restrict__ decbhh,
           const float* __restrict__ Wreg,   const float* __restrict__ breg,
           float* __restrict__ out)
{
    extern __shared__ float sm[];
    float* sW  = sm;              // slot0 Wih1 | slot1 Whh1 | slot2 Whh0 (off2 layout)
    float* sH  = sm + 49152;      // h0 [14][64], h1 @ +896
    float* qL1 = sm + 50944;      // layer1 gate sums [14][256] (original g index)
    float* qL0 = sm + 54528;      // layer0 raw sums  [14][256]

    const int tid   = threadIdx.x;
    const int g     = tid & 255;        // gate 0..255
    const int rh    = tid >> 8;         // row-half
    const int rbase = rh * 7;
    const int lt    = tid & 255;        // lane within row-half group
    const int b0    = blockIdx.x * NROW;

    // ---- init: pack encoder weights into smem ----
    for (int i = tid; i < 16384; i += RT) {
        int gg = i >> 6, k = i & 63;
        int d = off2(gg, k);
        sW[d]         = encWih[16384 + i];   // Wih1
        sW[16384 + d] = encWhh[16384 + i];   // Whh1
        sW[32768 + d] = encWhh[i];           // Whh0
    }
    for (int i = tid; i < 2 * 896; i += RT) sH[i] = 0.f;

    // ---- update-cell mapping: per rh 448 cells over 256 threads ----
    // cell A = lt (rows rbase+0..3), cell B = lt+256 (rows rbase+4..6, lt<192)
    const int rA = lt >> 6, uA = lt & 63;
    const bool hasB = (lt < 192);
    const int rB = rA + 4, uB = uA;
    const int qoffA = (rbase + rA) * G4_ + uA;
    const int qoffB = (rbase + rB) * G4_ + uB;
    float* h0pA = sH + (rbase + rA) * 64 + uA;
    float* h0pB = sH + (rbase + rB) * 64 + uB;
    float* h1pA = h0pA + 896;
    float* h1pB = h0pB + 896;

    // encoder layer-1 biases for cells (original gate indexing: u, 64+u, 128+u, 192+u)
    float4 eb1A, eb1B;
    eb1A.x = encbih[256 + uA]       + encbhh[256 + uA];
    eb1A.y = encbih[256 + 64 + uA]  + encbhh[256 + 64 + uA];
    eb1A.z = encbih[256 + 128 + uA] + encbhh[256 + 128 + uA];
    eb1A.w = encbih[256 + 192 + uA] + encbhh[256 + 192 + uA];
    eb1B = eb1A;   // uB == uA

    // x-part gmem offsets (pidx float4 layout), clamped for tail CTA
    int bA = b0 + rbase + rA; if (bA >= B_) bA = B_ - 1;
    int bB = b0 + rbase + rB; if (bB >= B_) bB = B_ - 1;
    const size_t gxoA = (size_t)bA * G4_ + (uA << 2);
    const size_t gxoB = (size_t)bB * G4_ + (uB << 2);
    __syncthreads();

    float4 gxA = *(const float4*)(d_g0 + gxoA);        // x(0)
    float4 gxB = hasB ? *(const float4*)(d_g0 + gxoB) : make_float4(0.f, 0.f, 0.f, 0.f);
    float c0A = 0.f, c1A = 0.f, c0B = 0.f, c1B = 0.f;

    // ---- prologue: h0(0) = lstm(x(0)) (h0(-1)=0) ----
    lstm4(gxA.x, gxA.y, gxA.z, gxA.w, c0A, h0pA);
    if (hasB) lstm4(gxB.x, gxB.y, gxB.z, gxB.w, c0B, h0pB);
    gxA = *(const float4*)(d_g0 + (size_t)1 * G0ROW + gxoA);   // x(1)
    if (hasB) gxB = *(const float4*)(d_g0 + (size_t)1 * G0ROW + gxoB);
    barh(rh);

    const float* hb0 = sH + rbase * 64;
    const float* hb1 = hb0 + 896;

    // -------------------- encoder fused supersteps s = 0..510 --------------------
    // M: a1 = Wih1·h0(s) + Whh1·h1(s-1) ; a0 = Whh0·h0(s)   (h0 loads shared)
    // U: h1(s) from a1+bias ; h0(s+1) from a0+x(s+1)
    for (int s = 0; s < T_ - 1; s++) {
        u64 a1[7], a0[7];
#pragma unroll
        for (int r = 0; r < 7; r++) { a1[r] = 0ull; a0[r] = 0ull; }
#pragma unroll
        for (int kq = 0; kq < 16; kq++) {
            const float* wp = sW + kq * 1024 + (g << 2);
            ulonglong2 wi = *(const ulonglong2*)(wp);
            ulonglong2 wh = *(const ulonglong2*)(wp + 16384);
            ulonglong2 w0 = *(const ulonglong2*)(wp + 32768);
            const float* hq = hb0 + kq * 4;
#pragma unroll
            for (int r = 0; r < 7; r++) {
                ulonglong2 h0v = *(const ulonglong2*)(hq + r * 64);
                ulonglong2 h1v = *(const ulonglong2*)(hq + 896 + r * 64);
                a1[r] = fma2(h0v.x, wi.x, a1[r]);
                a1[r] = fma2(h0v.y, wi.y, a1[r]);
                a1[r] = fma2(h1v.x, wh.x, a1[r]);
                a1[r] = fma2(h1v.y, wh.y, a1[r]);
                a0[r] = fma2(h0v.x, w0.x, a0[r]);
                a0[r] = fma2(h0v.y, w0.y, a0[r]);
            }
        }
#pragma unroll
        for (int r = 0; r < 7; r++) {
            qL1[(rbase + r) * G4_ + g] = hadd2(a1[r]);
            qL0[(rbase + r) * G4_ + g] = hadd2(a0[r]);
        }
        barh(rh);
        // ---- U ----
        {
            float gi = qL1[qoffA]       + eb1A.x;
            float gf = qL1[qoffA + 64]  + eb1A.y;
            float gg = qL1[qoffA + 128] + eb1A.z;
            float go = qL1[qoffA + 192] + eb1A.w;
            lstm4(gi, gf, gg, go, c1A, h1pA);
            gi = qL0[qoffA]       + gxA.x;
            gf = qL0[qoffA + 64]  + gxA.y;
            gg = qL0[qoffA + 128] + gxA.z;
            go = qL0[qoffA + 192] + gxA.w;
            lstm4(gi, gf, gg, go, c0A, h0pA);
        }
        if (hasB) {
            float gi = qL1[qoffB]       + eb1B.x;
            float gf = qL1[qoffB + 64]  + eb1B.y;
            float gg = qL1[qoffB + 128] + eb1B.z;
            float go = qL1[qoffB + 192] + eb1B.w;
            lstm4(gi, gf, gg, go, c1B, h1pB);
            gi = qL0[qoffB]       + gxB.x;
            gf = qL0[qoffB + 64]  + gxB.y;
            gg = qL0[qoffB + 128] + gxB.z;
            go = qL0[qoffB + 192] + gxB.w;
            lstm4(gi, gf, gg, go, c0B, h0pB);
        }
        if (s + 2 < T_) {      // prefetch x(s+2)
            gxA = *(const float4*)(d_g0 + (size_t)(s + 2) * G0ROW + gxoA);
            if (hasB) gxB = *(const float4*)(d_g0 + (size_t)(s + 2) * G0ROW + gxoB);
        }
        barh(rh);
    }

    // ---- epilogue: gates1(511) -> h1(511) ----
    {
        u64 a1[7];
#pragma unroll
        for (int r = 0; r < 7; r++) a1[r] = 0ull;
#pragma unroll
        for (int kq = 0; kq < 16; kq++) {
            const float* wp = sW + kq * 1024 + (g << 2);
            ulonglong2 wi = *(const ulonglong2*)(wp);
            ulonglong2 wh = *(const ulonglong2*)(wp + 16384);
            const float* hq = hb0 + kq * 4;
#pragma unroll
            for (int r = 0; r < 7; r++) {
                ulonglong2 h0v = *(const ulonglong2*)(hq + r * 64);
                ulonglong2 h1v = *(const ulonglong2*)(hq + 896 + r * 64);
                a1[r] = fma2(h0v.x, wi.x, a1[r]);
                a1[r] = fma2(h0v.y, wi.y, a1[r]);
                a1[r] = fma2(h1v.x, wh.x, a1[r]);
                a1[r] = fma2(h1v.y, wh.y, a1[r]);
            }
        }
#pragma unroll
        for (int r = 0; r < 7; r++) qL1[(rbase + r) * G4_ + g] = hadd2(a1[r]);
        barh(rh);
        {
            float gi = qL1[qoffA]       + eb1A.x;
            float gf = qL1[qoffA + 64]  + eb1A.y;
            float gg = qL1[qoffA + 128] + eb1A.z;
            float go = qL1[qoffA + 192] + eb1A.w;
            lstm4(gi, gf, gg, go, c1A, h1pA);
        }
        if (hasB) {
            float gi = qL1[qoffB]       + eb1B.x;
            float gf = qL1[qoffB + 64]  + eb1B.y;
            float gg = qL1[qoffB + 128] + eb1B.z;
            float go = qL1[qoffB + 192] + eb1B.w;
            lstm4(gi, gf, gg, go, c1B, h1pB);
        }
    }
    __syncthreads();   // full sync before overwriting sW (shared across rh)

    // -------------------- decoder setup --------------------
    // smem: slot0 dWih1 | slot1 dWhh1 | slot2 dWhh0 ; dWih0 streamed (d_wih0P)
    for (int i = tid; i < 16384; i += RT) {
        int gg = i >> 6, k = i & 63;
        int d = off2(gg, k);
        sW[d]         = decWih[16384 + i];
        sW[16384 + d] = decWhh[16384 + i];
        sW[32768 + d] = decWhh[i];
    }
    float4 db0A, db1A;
    db0A.x = decbih[uA]       + decbhh[uA];
    db0A.y = decbih[64 + uA]  + decbhh[64 + uA];
    db0A.z = decbih[128 + uA] + decbhh[128 + uA];
    db0A.w = decbih[192 + uA] + decbhh[192 + uA];
    db1A.x = decbih[256 + uA]       + decbhh[256 + uA];
    db1A.y = decbih[256 + 64 + uA]  + decbhh[256 + 64 + uA];
    db1A.z = decbih[256 + 128 + uA] + decbhh[256 + 128 + uA];
    db1A.w = decbih[256 + 192 + uA] + decbhh[256 + 192 + uA];
    c0A = c1A = c0B = c1B = 0.f;    // c reset; h carries over
    __syncthreads();

    // -------------------- decoder: 48 steps --------------------
    for (int t = 0; t < HOR_; t++) {
        // ---- M0: a = dWhh0(smem)·h0 + dWih0(gmem)·h1 ----
        {
            u64 a[7];
#pragma unroll
            for (int r = 0; r < 7; r++) a[r] = 0ull;
#pragma unroll
            for (int kq = 0; kq < 16; kq++) {
                ulonglong2 w0 = *(const ulonglong2*)(sW + 32768 + kq * 1024 + (g << 2));
                ulonglong2 wI = __ldg((const ulonglong2*)(d_wih0P + kq * 1024 + (g << 2)));
                const float* hq = hb0 + kq * 4;
#pragma unroll
                for (int r = 0; r < 7; r++) {
                    ulonglong2 h0v = *(const ulonglong2*)(hq + r * 64);
                    ulonglong2 h1v = *(const ulonglong2*)(hq + 896 + r * 64);
                    a[r] = fma2(h0v.x, w0.x, a[r]);
                    a[r] = fma2(h0v.y, w0.y, a[r]);
                    a[r] = fma2(h1v.x, wI.x, a[r]);
                    a[r] = fma2(h1v.y, wI.y, a[r]);
                }
            }
#pragma unroll
            for (int r = 0; r < 7; r++) qL0[(rbase + r) * G4_ + g] = hadd2(a[r]);
        }
        barh(rh);
        // ---- U0 ----
        {
            float gi = qL0[qoffA]       + db0A.x;
            float gf = qL0[qoffA + 64]  + db0A.y;
            float gg = qL0[qoffA + 128] + db0A.z;
            float go = qL0[qoffA + 192] + db0A.w;
            lstm4(gi, gf, gg, go, c0A, h0pA);
        }
        if (hasB) {
            float gi = qL0[qoffB]       + db0A.x;
            float gf = qL0[qoffB + 64]  + db0A.y;
            float gg = qL0[qoffB + 128] + db0A.z;
            float go = qL0[qoffB + 192] + db0A.w;
            lstm4(gi, gf, gg, go, c0B, h0pB);
        }
        barh(rh);
        // ---- M1: a = dWih1(smem)·h0 + dWhh1(smem)·h1 ----
        {
            u64 a[7];
#pragma unroll
            for (int r = 0; r < 7; r++) a[r] = 0ull;
#pragma unroll
            for (int kq = 0; kq < 16; kq++) {
                const float* wp = sW + kq * 1024 + (g << 2);
                ulonglong2 wi = *(const ulonglong2*)(wp);
                ulonglong2 wh = *(const ulonglong2*)(wp + 16384);
                const float* hq = hb0 + kq * 4;
#pragma unroll
                for (int r = 0; r < 7; r++) {
                    ulonglong2 h0v = *(const ulonglong2*)(hq + r * 64);
                    ulonglong2 h1v = *(const ulonglong2*)(hq + 896 + r * 64);
                    a[r] = fma2(h0v.x, wi.x, a[r]);
                    a[r] = fma2(h0v.y, wi.y, a[r]);
                    a[r] = fma2(h1v.x, wh.x, a[r]);
                    a[r] = fma2(h1v.y, wh.y, a[r]);
                }
            }
#pragma unroll
            for (int r = 0; r < 7; r++) qL1[(rbase + r) * G4_ + g] = hadd2(a[r]);
        }
        barh(rh);
        // ---- U1 ----
        {
            float gi = qL1[qoffA]       + db1A.x;
            float gf = qL1[qoffA + 64]  + db1A.y;
            float gg = qL1[qoffA + 128] + db1A.z;
            float go = qL1[qoffA + 192] + db1A.w;
            lstm4(gi, gf, gg, go, c1A, h1pA);
        }
        if (hasB) {
            float gi = qL1[qoffB]       + db1A.x;
            float gf = qL1[qoffB + 64]  + db1A.y;
            float gg = qL1[qoffB + 128] + db1A.z;
            float go = qL1[qoffB + 192] + db1A.w;
            lstm4(gi, gf, gg, go, c1B, h1pB);
        }
        barh(rh);
        // ---- regression head (rh-local rows; h1 synced by barh) ----
        if (lt < NROW * FOUT_ / 2) {
            int r = rbase + (lt >> 3), o = lt & 7;
            int b = b0 + r;
            if (b < B_) {
                float a = __ldg(&breg[o]);
                const float* hr = sH + 896 + r * 64;
#pragma unroll
                for (int k = 0; k < H_; k += 4) {
                    float4 h4 = *(const float4*)(hr + k);
                    float4 w4 = __ldg((const float4*)(Wreg + o * H_ + k));
                    a = fmaf(h4.x, w4.x, a);
                    a = fmaf(h4.y, w4.y, a);
                    a = fmaf(h4.z, w4.z, a);
                    a = fmaf(h4.w, w4.w, a);
                }
                out[((size_t)b * HOR_ + t) * FOUT_ + o] = a;
            }
        }
    }
}

// ---------------- launch ----------------
extern "C" void kernel_launch(void* const* d_in, const int* in_sizes, int n_in,
                              void* d_out, int out_size)
{
    const float* X      = (const float*)d_in[0];
    // d_in[1] = X_mask : all-ones, unused by reference
    const float* W_emb  = (const float*)d_in[2];
    const float* b_emb  = (const float*)d_in[3];
    const float* encWih = (const float*)d_in[4];
    const float* encWhh = (const float*)d_in[5];
    const float* encbih = (const float*)d_in[6];
    const float* encbhh = (const float*)d_in[7];
    const float* decWih = (const float*)d_in[8];
    const float* decWhh = (const float*)d_in[9];
    const float* decbih = (const float*)d_in[10];
    const float* decbhh = (const float*)d_in[11];
    const float* W_reg  = (const float*)d_in[12];
    const float* b_reg  = (const float*)d_in[13];
    float* out = (float*)d_out;

    cudaFuncSetAttribute(rnn_kernel, cudaFuncAttributeMaxDynamicSharedMemorySize, SMEM_BYTES);

    prep_kernel<<<FIN_ + 1, 256>>>(W_emb, b_emb, encWih, encbih, encbhh, decWih);
    emb_gemm<<<dim3(B_ / 128, T_), 256>>>(X);
    rnn_kernel<<<NCTA, RT, SMEM_BYTES>>>(encWih, encWhh, encbih, encbhh,
                                         decWih, decWhh, decbih, decbhh,
                                         W_reg, b_reg, out);
}

// round 15
// speedup vs baseline: 2.3505x; 1.9183x over previous
#include <cuda_runtime.h>
#include <cuda_fp16.h>

// Problem constants
#define B_    2048
#define T_    512
#define FIN_  32
#define H_    64
#define G4_   256        // 4*H
#define HOR_  48
#define FOUT_ 8
#define NROW  14         // batch rows per CTA (padded to 16 for MMA)
#define NCTA  147
#define RT    512
#define G0ROW (B_ * G4_)
#define QSTR  264        // qL row stride (f32), padded vs 256 to avoid bank conflicts

// ---------------- scratch (__device__ globals; no cudaMalloc allowed) ----------------
// d_g0 layout: [t][b][unit*4 + gate]  (float4 per hidden unit = {i,f,g,o})
__device__ float d_g0[(size_t)T_ * B_ * G4_];
__device__ float d_WcT[FIN_ * G4_];      // combined (Wih0 @ W_emb), pidx channel order
__device__ float d_bc[G4_];              // combined layer0 bias, pidx order
// fragment-major fp16 packed weights: 7 matrices x {hi,lo} x 8192 u32
// matrix ids: 0=eWih1 1=eWhh1 2=eWhh0 3=dWih1 4=dWhh1 5=dWhh0 6=dWih0
__device__ unsigned d_wpk[14 * 8192];

// ---------------- fast activations (exact-path, proven 2.9e-7) ----------------
__device__ __forceinline__ float sigf(float x) {
    return __fdividef(1.0f, 1.0f + __expf(-x));
}
__device__ __forceinline__ float tanh_f(float x) {
    return __fdividef(2.0f, 1.0f + __expf(-2.0f * x)) - 1.0f;
}

// packed output-channel index: gate g (0..255) -> unit*4 + gate_slot (x-part layout)
__device__ __forceinline__ int pidx(int g) { return ((g & 63) << 2) + (g >> 6); }

// ---------------- mma / ldmatrix helpers ----------------
__device__ __forceinline__ void mma8(float c[4], const unsigned a[4], uint2 b) {
    asm volatile("mma.sync.aligned.m16n8k16.row.col.f32.f16.f16.f32 "
        "{%0,%1,%2,%3}, {%4,%5,%6,%7}, {%8,%9}, {%0,%1,%2,%3};"
        : "+f"(c[0]), "+f"(c[1]), "+f"(c[2]), "+f"(c[3])
        : "r"(a[0]), "r"(a[1]), "r"(a[2]), "r"(a[3]), "r"(b.x), "r"(b.y));
}
__device__ __forceinline__ void ldm4(unsigned a[4], unsigned saddr) {
    asm volatile("ldmatrix.sync.aligned.m8n8.x4.shared.b16 {%0,%1,%2,%3}, [%4];"
        : "=r"(a[0]), "=r"(a[1]), "=r"(a[2]), "=r"(a[3]) : "r"(saddr));
}

// ---------------- prep: combined layer0 input weights / bias ----------------
__global__ void prep_kernel(const float* __restrict__ W_emb, const float* __restrict__ b_emb,
                            const float* __restrict__ encWih, const float* __restrict__ encbih,
                            const float* __restrict__ encbhh)
{
    int g  = threadIdx.x;   // original gate 0..255
    int bb = blockIdx.x;    // 0..32
    float wrow[H_];
#pragma unroll
    for (int h = 0; h < H_; h++) wrow[h] = encWih[g * H_ + h];

    if (bb == FIN_) {
        float b = encbih[g] + encbhh[g];
#pragma unroll
        for (int h = 0; h < H_; h++) b = fmaf(wrow[h], b_emb[h], b);
        d_bc[pidx(g)] = b;
    } else {
        int f = bb;
        float s = 0.f;
#pragma unroll
        for (int h = 0; h < H_; h++) s = fmaf(wrow[h], W_emb[h * FIN_ + f], s);
        d_WcT[f * G4_ + pidx(g)] = s;
    }
}

// ---------------- pack: fragment-major fp16 hi/lo weights ----------------
// element i of matrix-split ms: kt=i>>11, nt=(i>>6)&31, l=(i>>1)&31, j=i&1
// k = kt*16 + (l&3)*2 + j*8 ; gate n = nt*8 + l/4 ; value pair {W[n][k], W[n][k+1]}
__global__ void pack_kernel(const float* __restrict__ encWih, const float* __restrict__ encWhh,
                            const float* __restrict__ decWih, const float* __restrict__ decWhh)
{
    int ms = blockIdx.x;           // 0..13
    int m = ms >> 1, s = ms & 1;
    const float* src;
    switch (m) {
        case 0: src = encWih + 16384; break;
        case 1: src = encWhh + 16384; break;
        case 2: src = encWhh;         break;
        case 3: src = decWih + 16384; break;
        case 4: src = decWhh + 16384; break;
        case 5: src = decWhh;         break;
        default: src = decWih;        break;   // dWih0
    }
    for (int i = threadIdx.x; i < 8192; i += 256) {
        int kt = i >> 11, nt = (i >> 6) & 31, l = (i >> 1) & 31, j = i & 1;
        int k = kt * 16 + (l & 3) * 2 + j * 8;
        int n = nt * 8 + (l >> 2);
        float v0 = src[n * 64 + k], v1 = src[n * 64 + k + 1];
        __half h0 = __float2half_rn(v0), h1 = __float2half_rn(v1);
        __half2 o;
        if (s == 0) o = __halves2half2(h0, h1);
        else o = __halves2half2(__float2half_rn(v0 - __half2float(h0)),
                                __float2half_rn(v1 - __half2float(h1)));
        d_wpk[ms * 8192 + i] = *(unsigned*)&o;
    }
}

// ---------------- GEMM: d_g0[t][b][c] = X[b][t][:] @ WcT[:, c] + bc[c] ----------------
__global__ void __launch_bounds__(256)
emb_gemm(const float* __restrict__ X)
{
    __shared__ float sX[128 * FIN_];
    const int t   = blockIdx.y;
    const int b0  = blockIdx.x * 128;
    const int tid = threadIdx.x;

#pragma unroll
    for (int q = 0; q < 4; q++) {
        int lin = tid + q * 256;
        int rr = lin >> 3, f4 = lin & 7;
        float4 v = *(const float4*)(X + ((size_t)(b0 + rr) * T_ + t) * FIN_ + f4 * 4);
        *(float4*)(sX + rr * FIN_ + f4 * 4) = v;
    }
    float w[FIN_];
#pragma unroll
    for (int f = 0; f < FIN_; f++) w[f] = d_WcT[f * G4_ + tid];
    const float bias = d_bc[tid];
    __syncthreads();

    float* dst = d_g0 + (size_t)t * B_ * G4_ + (size_t)b0 * G4_ + tid;
#pragma unroll 2
    for (int rr = 0; rr < 128; rr++) {
        float a = bias;
        const float* xr = sX + rr * FIN_;
#pragma unroll
        for (int f = 0; f < FIN_; f += 4) {
            float4 x = *(const float4*)(xr + f);
            a = fmaf(x.x, w[f + 0], a);
            a = fmaf(x.y, w[f + 1], a);
            a = fmaf(x.z, w[f + 2], a);
            a = fmaf(x.w, w[f + 3], a);
        }
        dst[(size_t)rr * G4_] = a;
    }
}

// smem: sBW 6*32768B | h bufs 4*[16][72] half (9216B) | qL [16][QSTR] f32 (16896B)
#define SMEM_BYTES (196608 + 9216 + 16896)

__global__ void __launch_bounds__(RT, 1)
rnn_kernel(const float* __restrict__ encbih, const float* __restrict__ encbhh,
           const float* __restrict__ decbih, const float* __restrict__ decbhh,
           const float* __restrict__ Wreg,   const float* __restrict__ breg,
           float* __restrict__ out)
{
    extern __shared__ char smc[];
    unsigned* sBW = (unsigned*)smc;                 // 6 buffers x 8192 u32
    __half* hbuf  = (__half*)(smc + 196608);        // h0hi@0 h0lo@1152 h1hi@2304 h1lo@3456
    float*  qL    = (float*)(smc + 205824);         // [16][QSTR]

    const int tid  = threadIdx.x;
    const int w    = tid >> 5, l = tid & 31;
    const int grp  = l >> 2, tid4 = l & 3;
    const int b0   = blockIdx.x * NROW;

    // ---- copy encoder weights (matrices 0,1,2 hi/lo = first 49152 u32) ----
    {
        const uint4* s = (const uint4*)d_wpk;
        uint4* d = (uint4*)sBW;
        for (int i = tid; i < 12288; i += RT) d[i] = s[i];
    }
    // zero h buffers (4 x 1152 halfs)
    for (int i = tid; i < 2304; i += RT) ((unsigned*)hbuf)[i] = 0u;

    // ldmatrix per-lane base addresses (byte, shared space)
    const unsigned sb = (unsigned)__cvta_generic_to_shared(smc);
    const unsigned abase = sb + 196608 + (((l & 15) * 72 + ((l >> 1) & 8)) << 1);
    const unsigned h0hi_s = abase, h0lo_s = abase + 2304;
    const unsigned h1hi_s = abase + 4608, h1lo_s = abase + 6912;

    // B-frag base index (u32 units within one buffer) for this lane/warp
    const int fb0 = (2 * w) * 64 + l * 2;     // + kt*2048 per k-tile; ntile1 at +64

    // ---- update-cell mapping: cell A rows 0..7, cell B rows 8..13 (tid<384) ----
    const int rA = tid >> 6, uA = tid & 63;
    const bool hasB = (tid < 384);
    const int rB = 8 + (tid >> 6);

    // encoder L1 bias per cell (uB==uA)
    float4 eb1;
    eb1.x = encbih[256 + uA]       + encbhh[256 + uA];
    eb1.y = encbih[256 + 64 + uA]  + encbhh[256 + 64 + uA];
    eb1.z = encbih[256 + 128 + uA] + encbhh[256 + 128 + uA];
    eb1.w = encbih[256 + 192 + uA] + encbhh[256 + 192 + uA];

    // x-part gmem offsets (pidx float4 layout), clamped for tail CTA
    int bA = b0 + rA; if (bA >= B_) bA = B_ - 1;
    int bB = b0 + rB; if (bB >= B_) bB = B_ - 1;
    const size_t gxoA = (size_t)bA * G4_ + (uA << 2);
    const size_t gxoB = (size_t)bB * G4_ + (uA << 2);

    float4 gxA = *(const float4*)(d_g0 + gxoA);
    float4 gxB = hasB ? *(const float4*)(d_g0 + gxoB) : make_float4(0.f, 0.f, 0.f, 0.f);
    float c0A = 0.f, c1A = 0.f, c0B = 0.f, c1B = 0.f;
    __syncthreads();

    // -------------------- encoder: 512 steps --------------------
    for (int t = 0; t < T_; t++) {
        // ==== M0: C = Whh0 (bufs 4,5) x h0 ====
        {
            float Ca[4] = {0,0,0,0}, Cb[4] = {0,0,0,0};
#pragma unroll
            for (int kt = 0; kt < 4; kt++) {
                unsigned ah[4], al[4];
                ldm4(ah, h0hi_s + kt * 32);
                ldm4(al, h0lo_s + kt * 32);
                int fb = kt * 2048 + fb0;
                uint2 b;
                b = *(const uint2*)&sBW[4 * 8192 + fb];
                mma8(Ca, ah, b); mma8(Ca, al, b);
                b = *(const uint2*)&sBW[5 * 8192 + fb];
                mma8(Ca, ah, b);
                b = *(const uint2*)&sBW[4 * 8192 + fb + 64];
                mma8(Cb, ah, b); mma8(Cb, al, b);
                b = *(const uint2*)&sBW[5 * 8192 + fb + 64];
                mma8(Cb, ah, b);
            }
            float* q = qL + grp * QSTR + w * 16 + tid4 * 2;
            *(float2*)q        = make_float2(Ca[0], Ca[1]);
            *(float2*)(q + 8)  = make_float2(Cb[0], Cb[1]);
            float* q2 = q + 8 * QSTR;
            *(float2*)q2       = make_float2(Ca[2], Ca[3]);
            *(float2*)(q2 + 8) = make_float2(Cb[2], Cb[3]);
        }
        __syncthreads();
        // ==== U0: h0(t) = lstm(C + x(t)) ====
        {
            const float* qr = qL + rA * QSTR + uA;
            float gi = qr[0] + gxA.x, gf = qr[64] + gxA.y;
            float gg = qr[128] + gxA.z, go = qr[192] + gxA.w;
            float cn = sigf(gf) * c0A + sigf(gi) * tanh_f(gg);
            c0A = cn;
            float hn = sigf(go) * tanh_f(cn);
            __half hh = __float2half_rn(hn);
            hbuf[rA * 72 + uA] = hh;
            hbuf[1152 + rA * 72 + uA] = __float2half_rn(hn - __half2float(hh));
        }
        if (hasB) {
            const float* qr = qL + rB * QSTR + uA;
            float gi = qr[0] + gxB.x, gf = qr[64] + gxB.y;
            float gg = qr[128] + gxB.z, go = qr[192] + gxB.w;
            float cn = sigf(gf) * c0B + sigf(gi) * tanh_f(gg);
            c0B = cn;
            float hn = sigf(go) * tanh_f(cn);
            __half hh = __float2half_rn(hn);
            hbuf[rB * 72 + uA] = hh;
            hbuf[1152 + rB * 72 + uA] = __float2half_rn(hn - __half2float(hh));
        }
        if (t + 1 < T_) {
            gxA = *(const float4*)(d_g0 + (size_t)(t + 1) * G0ROW + gxoA);
            if (hasB) gxB = *(const float4*)(d_g0 + (size_t)(t + 1) * G0ROW + gxoB);
        }
        __syncthreads();
        // ==== M1: C = Wih1 (0,1) x h0 + Whh1 (2,3) x h1 ====
        {
            float Ca[4] = {0,0,0,0}, Cb[4] = {0,0,0,0};
#pragma unroll
            for (int kt = 0; kt < 4; kt++) {
                unsigned a0h[4], a0l[4], a1h[4], a1l[4];
                ldm4(a0h, h0hi_s + kt * 32);
                ldm4(a0l, h0lo_s + kt * 32);
                ldm4(a1h, h1hi_s + kt * 32);
                ldm4(a1l, h1lo_s + kt * 32);
                int fb = kt * 2048 + fb0;
                uint2 b;
                b = *(const uint2*)&sBW[0 * 8192 + fb];
                mma8(Ca, a0h, b); mma8(Ca, a0l, b);
                b = *(const uint2*)&sBW[1 * 8192 + fb];
                mma8(Ca, a0h, b);
                b = *(const uint2*)&sBW[2 * 8192 + fb];
                mma8(Ca, a1h, b); mma8(Ca, a1l, b);
                b = *(const uint2*)&sBW[3 * 8192 + fb];
                mma8(Ca, a1h, b);
                b = *(const uint2*)&sBW[0 * 8192 + fb + 64];
                mma8(Cb, a0h, b); mma8(Cb, a0l, b);
                b = *(const uint2*)&sBW[1 * 8192 + fb + 64];
                mma8(Cb, a0h, b);
                b = *(const uint2*)&sBW[2 * 8192 + fb + 64];
                mma8(Cb, a1h, b); mma8(Cb, a1l, b);
                b = *(const uint2*)&sBW[3 * 8192 + fb + 64];
                mma8(Cb, a1h, b);
            }
            float* q = qL + grp * QSTR + w * 16 + tid4 * 2;
            *(float2*)q        = make_float2(Ca[0], Ca[1]);
            *(float2*)(q + 8)  = make_float2(Cb[0], Cb[1]);
            float* q2 = q + 8 * QSTR;
            *(float2*)q2       = make_float2(Ca[2], Ca[3]);
            *(float2*)(q2 + 8) = make_float2(Cb[2], Cb[3]);
        }
        __syncthreads();
        // ==== U1: h1(t) = lstm(C + b1) ====
        {
            const float* qr = qL + rA * QSTR + uA;
            float gi = qr[0] + eb1.x, gf = qr[64] + eb1.y;
            float gg = qr[128] + eb1.z, go = qr[192] + eb1.w;
            float cn = sigf(gf) * c1A + sigf(gi) * tanh_f(gg);
            c1A = cn;
            float hn = sigf(go) * tanh_f(cn);
            __half hh = __float2half_rn(hn);
            hbuf[2304 + rA * 72 + uA] = hh;
            hbuf[3456 + rA * 72 + uA] = __float2half_rn(hn - __half2float(hh));
        }
        if (hasB) {
            const float* qr = qL + rB * QSTR + uA;
            float gi = qr[0] + eb1.x, gf = qr[64] + eb1.y;
            float gg = qr[128] + eb1.z, go = qr[192] + eb1.w;
            float cn = sigf(gf) * c1B + sigf(gi) * tanh_f(gg);
            c1B = cn;
            float hn = sigf(go) * tanh_f(cn);
            __half hh = __float2half_rn(hn);
            hbuf[2304 + rB * 72 + uA] = hh;
            hbuf[3456 + rB * 72 + uA] = __float2half_rn(hn - __half2float(hh));
        }
        __syncthreads();
    }

    // -------------------- decoder setup --------------------
    {
        const uint4* s = (const uint4*)(d_wpk + 49152);   // matrices 3,4,5 hi/lo
        uint4* d = (uint4*)sBW;
        for (int i = tid; i < 12288; i += RT) d[i] = s[i];
    }
    float4 db0, db1;
    db0.x = decbih[uA]       + decbhh[uA];
    db0.y = decbih[64 + uA]  + decbhh[64 + uA];
    db0.z = decbih[128 + uA] + decbhh[128 + uA];
    db0.w = decbih[192 + uA] + decbhh[192 + uA];
    db1.x = decbih[256 + uA]       + decbhh[256 + uA];
    db1.y = decbih[256 + 64 + uA]  + decbhh[256 + 64 + uA];
    db1.z = decbih[256 + 128 + uA] + decbhh[256 + 128 + uA];
    db1.w = decbih[256 + 192 + uA] + decbhh[256 + 192 + uA];
    c0A = c1A = c0B = c1B = 0.f;      // c reset; h carries over
    __syncthreads();

    // -------------------- decoder: 48 steps --------------------
    // smem now: [0,1]=dWih1 hi/lo, [2,3]=dWhh1 hi/lo, [4,5]=dWhh0 hi/lo; dWih0 from gmem (12,13)
    for (int t = 0; t < HOR_; t++) {
        // ==== M0: dWhh0 x h0 + dWih0(gmem) x h1 ====
        {
            float Ca[4] = {0,0,0,0}, Cb[4] = {0,0,0,0};
#pragma unroll
            for (int kt = 0; kt < 4; kt++) {
                unsigned a0h[4], a0l[4], a1h[4], a1l[4];
                ldm4(a0h, h0hi_s + kt * 32);
                ldm4(a0l, h0lo_s + kt * 32);
                ldm4(a1h, h1hi_s + kt * 32);
                ldm4(a1l, h1lo_s + kt * 32);
                int fb = kt * 2048 + fb0;
                uint2 b;
                b = *(const uint2*)&sBW[4 * 8192 + fb];
                mma8(Ca, a0h, b); mma8(Ca, a0l, b);
                b = *(const uint2*)&sBW[5 * 8192 + fb];
                mma8(Ca, a0h, b);
                uint2 g1 = __ldg((const uint2*)&d_wpk[12 * 8192 + fb]);
                mma8(Ca, a1h, g1); mma8(Ca, a1l, g1);
                uint2 g2 = __ldg((const uint2*)&d_wpk[13 * 8192 + fb]);
                mma8(Ca, a1h, g2);
                b = *(const uint2*)&sBW[4 * 8192 + fb + 64];
                mma8(Cb, a0h, b); mma8(Cb, a0l, b);
                b = *(const uint2*)&sBW[5 * 8192 + fb + 64];
                mma8(Cb, a0h, b);
                g1 = __ldg((const uint2*)&d_wpk[12 * 8192 + fb + 64]);
                mma8(Cb, a1h, g1); mma8(Cb, a1l, g1);
                g2 = __ldg((const uint2*)&d_wpk[13 * 8192 + fb + 64]);
                mma8(Cb, a1h, g2);
            }
            float* q = qL + grp * QSTR + w * 16 + tid4 * 2;
            *(float2*)q        = make_float2(Ca[0], Ca[1]);
            *(float2*)(q + 8)  = make_float2(Cb[0], Cb[1]);
            float* q2 = q + 8 * QSTR;
            *(float2*)q2       = make_float2(Ca[2], Ca[3]);
            *(float2*)(q2 + 8) = make_float2(Cb[2], Cb[3]);
        }
        __syncthreads();
        // ==== U0 ====
        {
            const float* qr = qL + rA * QSTR + uA;
            float gi = qr[0] + db0.x, gf = qr[64] + db0.y;
            float gg = qr[128] + db0.z, go = qr[192] + db0.w;
            float cn = sigf(gf) * c0A + sigf(gi) * tanh_f(gg);
            c0A = cn;
            float hn = sigf(go) * tanh_f(cn);
            __half hh = __float2half_rn(hn);
            hbuf[rA * 72 + uA] = hh;
            hbuf[1152 + rA * 72 + uA] = __float2half_rn(hn - __half2float(hh));
        }
        if (hasB) {
            const float* qr = qL + rB * QSTR + uA;
            float gi = qr[0] + db0.x, gf = qr[64] + db0.y;
            float gg = qr[128] + db0.z, go = qr[192] + db0.w;
            float cn = sigf(gf) * c0B + sigf(gi) * tanh_f(gg);
            c0B = cn;
            float hn = sigf(go) * tanh_f(cn);
            __half hh = __float2half_rn(hn);
            hbuf[rB * 72 + uA] = hh;
            hbuf[1152 + rB * 72 + uA] = __float2half_rn(hn - __half2float(hh));
        }
        __syncthreads();
        // ==== M1: dWih1 x h0 + dWhh1 x h1 (same as encoder M1) ====
        {
            float Ca[4] = {0,0,0,0}, Cb[4] = {0,0,0,0};
#pragma unroll
            for (int kt = 0; kt < 4; kt++) {
                unsigned a0h[4], a0l[4], a1h[4], a1l[4];
                ldm4(a0h, h0hi_s + kt * 32);
                ldm4(a0l, h0lo_s + kt * 32);
                ldm4(a1h, h1hi_s + kt * 32);
                ldm4(a1l, h1lo_s + kt * 32);
                int fb = kt * 2048 + fb0;
                uint2 b;
                b = *(const uint2*)&sBW[0 * 8192 + fb];
                mma8(Ca, a0h, b); mma8(Ca, a0l, b);
                b = *(const uint2*)&sBW[1 * 8192 + fb];
                mma8(Ca, a0h, b);
                b = *(const uint2*)&sBW[2 * 8192 + fb];
                mma8(Ca, a1h, b); mma8(Ca, a1l, b);
                b = *(const uint2*)&sBW[3 * 8192 + fb];
                mma8(Ca, a1h, b);
                b = *(const uint2*)&sBW[0 * 8192 + fb + 64];
                mma8(Cb, a0h, b); mma8(Cb, a0l, b);
                b = *(const uint2*)&sBW[1 * 8192 + fb + 64];
                mma8(Cb, a0h, b);
                b = *(const uint2*)&sBW[2 * 8192 + fb + 64];
                mma8(Cb, a1h, b); mma8(Cb, a1l, b);
                b = *(const uint2*)&sBW[3 * 8192 + fb + 64];
                mma8(Cb, a1h, b);
            }
            float* q = qL + grp * QSTR + w * 16 + tid4 * 2;
            *(float2*)q        = make_float2(Ca[0], Ca[1]);
            *(float2*)(q + 8)  = make_float2(Cb[0], Cb[1]);
            float* q2 = q + 8 * QSTR;
            *(float2*)q2       = make_float2(Ca[2], Ca[3]);
            *(float2*)(q2 + 8) = make_float2(Cb[2], Cb[3]);
        }
        __syncthreads();
        // ==== U1 ====
        {
            const float* qr = qL + rA * QSTR + uA;
            float gi = qr[0] + db1.x, gf = qr[64] + db1.y;
            float gg = qr[128] + db1.z, go = qr[192] + db1.w;
            float cn = sigf(gf) * c1A + sigf(gi) * tanh_f(gg);
            c1A = cn;
            float hn = sigf(go) * tanh_f(cn);
            __half hh = __float2half_rn(hn);
            hbuf[2304 + rA * 72 + uA] = hh;
            hbuf[3456 + rA * 72 + uA] = __float2half_rn(hn - __half2float(hh));
        }
        if (hasB) {
            const float* qr = qL + rB * QSTR + uA;
            float gi = qr[0] + db1.x, gf = qr[64] + db1.y;
            float gg = qr[128] + db1.z, go = qr[192] + db1.w;
            float cn = sigf(gf) * c1B + sigf(gi) * tanh_f(gg);
            c1B = cn;
            float hn = sigf(go) * tanh_f(cn);
            __half hh = __float2half_rn(hn);
            hbuf[2304 + rB * 72 + uA] = hh;
            hbuf[3456 + rB * 72 + uA] = __float2half_rn(hn - __half2float(hh));
        }
        __syncthreads();
        // ==== regression head: y = h1 @ Wreg^T + breg ====
        if (tid < NROW * FOUT_) {
            int r = tid >> 3, o = tid & 7;
            int b = b0 + r;
            if (b < B_) {
                float a = __ldg(&breg[o]);
#pragma unroll
                for (int k = 0; k < H_; k++) {
                    float hk = __half2float(hbuf[2304 + r * 72 + k])
                             + __half2float(hbuf[3456 + r * 72 + k]);
                    a = fmaf(hk, __ldg(&Wreg[o * H_ + k]), a);
                }
                out[((size_t)b * HOR_ + t) * FOUT_ + o] = a;
            }
        }
    }
}

// ---------------- launch ----------------
extern "C" void kernel_launch(void* const* d_in, const int* in_sizes, int n_in,
                              void* d_out, int out_size)
{
    const float* X      = (const float*)d_in[0];
    // d_in[1] = X_mask : all-ones, unused by reference
    const float* W_emb  = (const float*)d_in[2];
    const float* b_emb  = (const float*)d_in[3];
    const float* encWih = (const float*)d_in[4];
    const float* encWhh = (const float*)d_in[5];
    const float* encbih = (const float*)d_in[6];
    const float* encbhh = (const float*)d_in[7];
    const float* decWih = (const float*)d_in[8];
    const float* decWhh = (const float*)d_in[9];
    const float* decbih = (const float*)d_in[10];
    const float* decbhh = (const float*)d_in[11];
    const float* W_reg  = (const float*)d_in[12];
    const float* b_reg  = (const float*)d_in[13];
    float* out = (float*)d_out;

    cudaFuncSetAttribute(rnn_kernel, cudaFuncAttributeMaxDynamicSharedMemorySize, SMEM_BYTES);

    prep_kernel<<<FIN_ + 1, 256>>>(W_emb, b_emb, encWih, encbih, encbhh);
    pack_kernel<<<14, 256>>>(encWih, encWhh, decWih, decWhh);
    emb_gemm<<<dim3(B_ / 128, T_), 256>>>(X);
    rnn_kernel<<<NCTA, RT, SMEM_BYTES>>>(encbih, encbhh, decbih, decbhh,
                                         W_reg, b_reg, out);
}

// round 16
// speedup vs baseline: 2.5704x; 1.0936x over previous
#include <cuda_runtime.h>
#include <cuda_fp16.h>

// Problem constants
#define B_    2048
#define T_    512
#define FIN_  32
#define H_    64
#define G4_   256        // 4*H
#define HOR_  48
#define FOUT_ 8
#define NROW  14         // batch rows per CTA (padded to 16 for MMA)
#define NCTA  147
#define RT    512
#define G0ROW (B_ * G4_)
#define QSTR  264        // qL row stride (f32), padded vs 256 to avoid bank conflicts

// ---------------- scratch (__device__ globals; no cudaMalloc allowed) ----------------
// d_g0 layout: [t][b][unit*4 + gate]  (float4 per hidden unit = {i,f,g,o})
__device__ float d_g0[(size_t)T_ * B_ * G4_];
__device__ float d_WcT[FIN_ * G4_];      // combined (Wih0 @ W_emb), pidx channel order
__device__ float d_bc[G4_];              // combined layer0 bias, pidx order
// fragment-major fp16 packed weights: 7 matrices x {hi,lo} x 8192 u32
// matrix-split ids: 0/1=eWih1 2/3=eWhh1 4/5=eWhh0 6/7=dWih1 8/9=dWhh1 10/11=dWhh0 12/13=dWih0
__device__ unsigned d_wpk[14 * 8192];

// ---------------- fast activations ----------------
__device__ __forceinline__ float sigf(float x) {
    return __fdividef(1.0f, 1.0f + __expf(-x));
}
__device__ __forceinline__ float tanh_f(float x) {
    return __fdividef(2.0f, 1.0f + __expf(-2.0f * x)) - 1.0f;
}

// packed output-channel index: gate g (0..255) -> unit*4 + gate_slot (x-part layout)
__device__ __forceinline__ int pidx(int g) { return ((g & 63) << 2) + (g >> 6); }

// ---------------- mma / ldmatrix helpers ----------------
__device__ __forceinline__ void mma8(float c[4], const unsigned a[4], uint2 b) {
    asm volatile("mma.sync.aligned.m16n8k16.row.col.f32.f16.f16.f32 "
        "{%0,%1,%2,%3}, {%4,%5,%6,%7}, {%8,%9}, {%0,%1,%2,%3};"
        : "+f"(c[0]), "+f"(c[1]), "+f"(c[2]), "+f"(c[3])
        : "r"(a[0]), "r"(a[1]), "r"(a[2]), "r"(a[3]), "r"(b.x), "r"(b.y));
}
__device__ __forceinline__ void ldm4(unsigned a[4], unsigned saddr) {
    asm volatile("ldmatrix.sync.aligned.m8n8.x4.shared.b16 {%0,%1,%2,%3}, [%4];"
        : "=r"(a[0]), "=r"(a[1]), "=r"(a[2]), "=r"(a[3]) : "r"(saddr));
}

// ---------------- prep: combined layer0 input weights / bias ----------------
__global__ void prep_kernel(const float* __restrict__ W_emb, const float* __restrict__ b_emb,
                            const float* __restrict__ encWih, const float* __restrict__ encbih,
                            const float* __restrict__ encbhh)
{
    int g  = threadIdx.x;
    int bb = blockIdx.x;
    float wrow[H_];
#pragma unroll
    for (int h = 0; h < H_; h++) wrow[h] = encWih[g * H_ + h];

    if (bb == FIN_) {
        float b = encbih[g] + encbhh[g];
#pragma unroll
        for (int h = 0; h < H_; h++) b = fmaf(wrow[h], b_emb[h], b);
        d_bc[pidx(g)] = b;
    } else {
        int f = bb;
        float s = 0.f;
#pragma unroll
        for (int h = 0; h < H_; h++) s = fmaf(wrow[h], W_emb[h * FIN_ + f], s);
        d_WcT[f * G4_ + pidx(g)] = s;
    }
}

// ---------------- pack: fragment-major fp16 hi/lo weights ----------------
__global__ void pack_kernel(const float* __restrict__ encWih, const float* __restrict__ encWhh,
                            const float* __restrict__ decWih, const float* __restrict__ decWhh)
{
    int ms = blockIdx.x;           // 0..13
    int m = ms >> 1, s = ms & 1;
    const float* src;
    switch (m) {
        case 0: src = encWih + 16384; break;
        case 1: src = encWhh + 16384; break;
        case 2: src = encWhh;         break;
        case 3: src = decWih + 16384; break;
        case 4: src = decWhh + 16384; break;
        case 5: src = decWhh;         break;
        default: src = decWih;        break;   // dWih0
    }
    for (int i = threadIdx.x; i < 8192; i += 256) {
        int kt = i >> 11, nt = (i >> 6) & 31, l = (i >> 1) & 31, j = i & 1;
        int k = kt * 16 + (l & 3) * 2 + j * 8;
        int n = nt * 8 + (l >> 2);
        float v0 = src[n * 64 + k], v1 = src[n * 64 + k + 1];
        __half h0 = __float2half_rn(v0), h1 = __float2half_rn(v1);
        __half2 o;
        if (s == 0) o = __halves2half2(h0, h1);
        else o = __halves2half2(__float2half_rn(v0 - __half2float(h0)),
                                __float2half_rn(v1 - __half2float(h1)));
        d_wpk[ms * 8192 + i] = *(unsigned*)&o;
    }
}

// ---------------- GEMM: d_g0[t][b][c] = X[b][t][:] @ WcT[:, c] + bc[c] ----------------
__global__ void __launch_bounds__(256)
emb_gemm(const float* __restrict__ X)
{
    __shared__ float sX[128 * FIN_];
    const int t   = blockIdx.y;
    const int b0  = blockIdx.x * 128;
    const int tid = threadIdx.x;

#pragma unroll
    for (int q = 0; q < 4; q++) {
        int lin = tid + q * 256;
        int rr = lin >> 3, f4 = lin & 7;
        float4 v = *(const float4*)(X + ((size_t)(b0 + rr) * T_ + t) * FIN_ + f4 * 4);
        *(float4*)(sX + rr * FIN_ + f4 * 4) = v;
    }
    float w[FIN_];
#pragma unroll
    for (int f = 0; f < FIN_; f++) w[f] = d_WcT[f * G4_ + tid];
    const float bias = d_bc[tid];
    __syncthreads();

    float* dst = d_g0 + (size_t)t * B_ * G4_ + (size_t)b0 * G4_ + tid;
#pragma unroll 2
    for (int rr = 0; rr < 128; rr++) {
        float a = bias;
        const float* xr = sX + rr * FIN_;
#pragma unroll
        for (int f = 0; f < FIN_; f += 4) {
            float4 x = *(const float4*)(xr + f);
            a = fmaf(x.x, w[f + 0], a);
            a = fmaf(x.y, w[f + 1], a);
            a = fmaf(x.z, w[f + 2], a);
            a = fmaf(x.w, w[f + 3], a);
        }
        dst[(size_t)rr * G4_] = a;
    }
}

// smem: sBW 5*32768B | hbuf 4*[16][72] half (9216B) | qL0 16896B | qL1 16896B
#define SMEM_BYTES (163840 + 9216 + 16896 + 16896)

__global__ void __launch_bounds__(RT, 1)
rnn_kernel(const float* __restrict__ encbih, const float* __restrict__ encbhh,
           const float* __restrict__ decbih, const float* __restrict__ decbhh,
           const float* __restrict__ Wreg,   const float* __restrict__ breg,
           float* __restrict__ out)
{
    extern __shared__ char smc[];
    unsigned* sBW = (unsigned*)smc;                 // 5 buffers x 8192 u32
    __half* hbuf  = (__half*)(smc + 163840);        // h0hi@0 h0lo@1152 h1hi@2304 h1lo@3456
    float*  qL0   = (float*)(smc + 173056);         // [16][QSTR]
    float*  qL1   = (float*)(smc + 189952);         // [16][QSTR]

    const int tid  = threadIdx.x;
    const int w    = tid >> 5, l = tid & 31;
    const int grp  = l >> 2, tid4 = l & 3;
    const int b0   = blockIdx.x * NROW;

    // ---- copy encoder weights: ms0..4 (eWih1 hi/lo, eWhh1 hi/lo, eWhh0 hi) ----
    {
        const uint4* s = (const uint4*)d_wpk;
        uint4* d = (uint4*)sBW;
        for (int i = tid; i < 10240; i += RT) d[i] = s[i];
    }
    for (int i = tid; i < 2304; i += RT) ((unsigned*)hbuf)[i] = 0u;

    // ldmatrix per-lane base addresses
    const unsigned sb = (unsigned)__cvta_generic_to_shared(smc);
    const unsigned abase = sb + 163840 + (((l & 15) * 72 + ((l >> 1) & 8)) << 1);
    const unsigned h0hi_s = abase, h0lo_s = abase + 2304;
    const unsigned h1hi_s = abase + 4608, h1lo_s = abase + 6912;

    const int fb0 = (2 * w) * 64 + l * 2;

    // ---- update-cell mapping ----
    const int rA = tid >> 6, uA = tid & 63;
    const bool hasB = (tid < 384);
    const int rB = 8 + (tid >> 6);

    float4 eb1;
    eb1.x = encbih[256 + uA]       + encbhh[256 + uA];
    eb1.y = encbih[256 + 64 + uA]  + encbhh[256 + 64 + uA];
    eb1.z = encbih[256 + 128 + uA] + encbhh[256 + 128 + uA];
    eb1.w = encbih[256 + 192 + uA] + encbhh[256 + 192 + uA];

    int bA = b0 + rA; if (bA >= B_) bA = B_ - 1;
    int bB = b0 + rB; if (bB >= B_) bB = B_ - 1;
    const size_t gxoA = (size_t)bA * G4_ + (uA << 2);
    const size_t gxoB = (size_t)bB * G4_ + (uA << 2);

    float4 gxA = *(const float4*)(d_g0 + gxoA);           // x(0)
    float4 gxB = hasB ? *(const float4*)(d_g0 + gxoB) : make_float4(0.f, 0.f, 0.f, 0.f);
    float c0A = 0.f, c1A = 0.f, c0B = 0.f, c1B = 0.f;
    __syncthreads();

    // ---- prologue: h0(0) = lstm(x(0)) ----
    {
        float cn = sigf(gxA.y) * c0A + sigf(gxA.x) * tanh_f(gxA.z);
        c0A = cn;
        float hn = sigf(gxA.w) * tanh_f(cn);
        __half hh = __float2half_rn(hn);
        hbuf[rA * 72 + uA] = hh;
        hbuf[1152 + rA * 72 + uA] = __float2half_rn(hn - __half2float(hh));
    }
    if (hasB) {
        float cn = sigf(gxB.y) * c0B + sigf(gxB.x) * tanh_f(gxB.z);
        c0B = cn;
        float hn = sigf(gxB.w) * tanh_f(cn);
        __half hh = __float2half_rn(hn);
        hbuf[rB * 72 + uA] = hh;
        hbuf[1152 + rB * 72 + uA] = __float2half_rn(hn - __half2float(hh));
    }
    gxA = *(const float4*)(d_g0 + (size_t)1 * G0ROW + gxoA);   // x(1)
    if (hasB) gxB = *(const float4*)(d_g0 + (size_t)1 * G0ROW + gxoB);
    __syncthreads();

    // -------------------- encoder fused supersteps s = 0..510 --------------------
    // MM: qL1 = Wih1*h0(s) + Whh1*h1(s-1) ; qL0 = Whh0*h0(s)   [eWhh0_lo from gmem]
    // U : h1(s) from qL1+bias ; h0(s+1) from qL0+x(s+1)
    for (int s = 0; s < T_ - 1; s++) {
        float C1a[4] = {0,0,0,0}, C1b[4] = {0,0,0,0};
        float C0a[4] = {0,0,0,0}, C0b[4] = {0,0,0,0};
#pragma unroll
        for (int kt = 0; kt < 4; kt++) {
            int fb = kt * 2048 + fb0;
            {
                unsigned a0h[4], a0l[4];
                ldm4(a0h, h0hi_s + kt * 32);
                ldm4(a0l, h0lo_s + kt * 32);
                uint2 b;
                b = *(const uint2*)&sBW[0 * 8192 + fb];
                mma8(C1a, a0h, b); mma8(C1a, a0l, b);
                b = *(const uint2*)&sBW[1 * 8192 + fb];
                mma8(C1a, a0h, b);
                b = *(const uint2*)&sBW[0 * 8192 + fb + 64];
                mma8(C1b, a0h, b); mma8(C1b, a0l, b);
                b = *(const uint2*)&sBW[1 * 8192 + fb + 64];
                mma8(C1b, a0h, b);
                b = *(const uint2*)&sBW[4 * 8192 + fb];
                mma8(C0a, a0h, b); mma8(C0a, a0l, b);
                uint2 g = __ldg((const uint2*)&d_wpk[5 * 8192 + fb]);
                mma8(C0a, a0h, g);
                b = *(const uint2*)&sBW[4 * 8192 + fb + 64];
                mma8(C0b, a0h, b); mma8(C0b, a0l, b);
                g = __ldg((const uint2*)&d_wpk[5 * 8192 + fb + 64]);
                mma8(C0b, a0h, g);
            }
            {
                unsigned a1h[4], a1l[4];
                ldm4(a1h, h1hi_s + kt * 32);
                ldm4(a1l, h1lo_s + kt * 32);
                uint2 b;
                b = *(const uint2*)&sBW[2 * 8192 + fb];
                mma8(C1a, a1h, b); mma8(C1a, a1l, b);
                b = *(const uint2*)&sBW[3 * 8192 + fb];
                mma8(C1a, a1h, b);
                b = *(const uint2*)&sBW[2 * 8192 + fb + 64];
                mma8(C1b, a1h, b); mma8(C1b, a1l, b);
                b = *(const uint2*)&sBW[3 * 8192 + fb + 64];
                mma8(C1b, a1h, b);
            }
        }
        {
            float* q = qL1 + grp * QSTR + w * 16 + tid4 * 2;
            *(float2*)q        = make_float2(C1a[0], C1a[1]);
            *(float2*)(q + 8)  = make_float2(C1b[0], C1b[1]);
            float* q2 = q + 8 * QSTR;
            *(float2*)q2       = make_float2(C1a[2], C1a[3]);
            *(float2*)(q2 + 8) = make_float2(C1b[2], C1b[3]);
            float* p = qL0 + grp * QSTR + w * 16 + tid4 * 2;
            *(float2*)p        = make_float2(C0a[0], C0a[1]);
            *(float2*)(p + 8)  = make_float2(C0b[0], C0b[1]);
            float* p2 = p + 8 * QSTR;
            *(float2*)p2       = make_float2(C0a[2], C0a[3]);
            *(float2*)(p2 + 8) = make_float2(C0b[2], C0b[3]);
        }
        __syncthreads();
        // ---- U: h1(s), then h0(s+1) ----
        {
            const float* qr = qL1 + rA * QSTR + uA;
            float gi = qr[0] + eb1.x, gf = qr[64] + eb1.y;
            float gg = qr[128] + eb1.z, go = qr[192] + eb1.w;
            float cn = sigf(gf) * c1A + sigf(gi) * tanh_f(gg);
            c1A = cn;
            float hn = sigf(go) * tanh_f(cn);
            __half hh = __float2half_rn(hn);
            hbuf[2304 + rA * 72 + uA] = hh;
            hbuf[3456 + rA * 72 + uA] = __float2half_rn(hn - __half2float(hh));
            const float* pr = qL0 + rA * QSTR + uA;
            gi = pr[0] + gxA.x; gf = pr[64] + gxA.y;
            gg = pr[128] + gxA.z; go = pr[192] + gxA.w;
            cn = sigf(gf) * c0A + sigf(gi) * tanh_f(gg);
            c0A = cn;
            hn = sigf(go) * tanh_f(cn);
            hh = __float2half_rn(hn);
            hbuf[rA * 72 + uA] = hh;
            hbuf[1152 + rA * 72 + uA] = __float2half_rn(hn - __half2float(hh));
        }
        if (hasB) {
            const float* qr = qL1 + rB * QSTR + uA;
            float gi = qr[0] + eb1.x, gf = qr[64] + eb1.y;
            float gg = qr[128] + eb1.z, go = qr[192] + eb1.w;
            float cn = sigf(gf) * c1B + sigf(gi) * tanh_f(gg);
            c1B = cn;
            float hn = sigf(go) * tanh_f(cn);
            __half hh = __float2half_rn(hn);
            hbuf[2304 + rB * 72 + uA] = hh;
            hbuf[3456 + rB * 72 + uA] = __float2half_rn(hn - __half2float(hh));
            const float* pr = qL0 + rB * QSTR + uA;
            gi = pr[0] + gxB.x; gf = pr[64] + gxB.y;
            gg = pr[128] + gxB.z; go = pr[192] + gxB.w;
            cn = sigf(gf) * c0B + sigf(gi) * tanh_f(gg);
            c0B = cn;
            hn = sigf(go) * tanh_f(cn);
            hh = __float2half_rn(hn);
            hbuf[rB * 72 + uA] = hh;
            hbuf[1152 + rB * 72 + uA] = __float2half_rn(hn - __half2float(hh));
        }
        if (s + 2 < T_) {   // prefetch x(s+2)
            gxA = *(const float4*)(d_g0 + (size_t)(s + 2) * G0ROW + gxoA);
            if (hasB) gxB = *(const float4*)(d_g0 + (size_t)(s + 2) * G0ROW + gxoB);
        }
        __syncthreads();
    }

    // ---- epilogue: qL1(511) -> h1(511) ----
    {
        float C1a[4] = {0,0,0,0}, C1b[4] = {0,0,0,0};
#pragma unroll
        for (int kt = 0; kt < 4; kt++) {
            int fb = kt * 2048 + fb0;
            unsigned a0h[4], a0l[4], a1h[4], a1l[4];
            ldm4(a0h, h0hi_s + kt * 32);
            ldm4(a0l, h0lo_s + kt * 32);
            ldm4(a1h, h1hi_s + kt * 32);
            ldm4(a1l, h1lo_s + kt * 32);
            uint2 b;
            b = *(const uint2*)&sBW[0 * 8192 + fb];
            mma8(C1a, a0h, b); mma8(C1a, a0l, b);
            b = *(const uint2*)&sBW[1 * 8192 + fb];
            mma8(C1a, a0h, b);
            b = *(const uint2*)&sBW[2 * 8192 + fb];
            mma8(C1a, a1h, b); mma8(C1a, a1l, b);
            b = *(const uint2*)&sBW[3 * 8192 + fb];
            mma8(C1a, a1h, b);
            b = *(const uint2*)&sBW[0 * 8192 + fb + 64];
            mma8(C1b, a0h, b); mma8(C1b, a0l, b);
            b = *(const uint2*)&sBW[1 * 8192 + fb + 64];
            mma8(C1b, a0h, b);
            b = *(const uint2*)&sBW[2 * 8192 + fb + 64];
            mma8(C1b, a1h, b); mma8(C1b, a1l, b);
            b = *(const uint2*)&sBW[3 * 8192 + fb + 64];
            mma8(C1b, a1h, b);
        }
        float* q = qL1 + grp * QSTR + w * 16 + tid4 * 2;
        *(float2*)q        = make_float2(C1a[0], C1a[1]);
        *(float2*)(q + 8)  = make_float2(C1b[0], C1b[1]);
        float* q2 = q + 8 * QSTR;
        *(float2*)q2       = make_float2(C1a[2], C1a[3]);
        *(float2*)(q2 + 8) = make_float2(C1b[2], C1b[3]);
        __syncthreads();
        {
            const float* qr = qL1 + rA * QSTR + uA;
            float gi = qr[0] + eb1.x, gf = qr[64] + eb1.y;
            float gg = qr[128] + eb1.z, go = qr[192] + eb1.w;
            float cn = sigf(gf) * c1A + sigf(gi) * tanh_f(gg);
            c1A = cn;
            float hn = sigf(go) * tanh_f(cn);
            __half hh = __float2half_rn(hn);
            hbuf[2304 + rA * 72 + uA] = hh;
            hbuf[3456 + rA * 72 + uA] = __float2half_rn(hn - __half2float(hh));
        }
        if (hasB) {
            const float* qr = qL1 + rB * QSTR + uA;
            float gi = qr[0] + eb1.x, gf = qr[64] + eb1.y;
            float gg = qr[128] + eb1.z, go = qr[192] + eb1.w;
            float cn = sigf(gf) * c1B + sigf(gi) * tanh_f(gg);
            c1B = cn;
            float hn = sigf(go) * tanh_f(cn);
            __half hh = __float2half_rn(hn);
            hbuf[2304 + rB * 72 + uA] = hh;
            hbuf[3456 + rB * 72 + uA] = __float2half_rn(hn - __half2float(hh));
        }
        __syncthreads();
    }

    // -------------------- decoder setup --------------------
    // smem bufs: 0/1=dWih1 hi/lo (ms6,7), 2/3=dWhh1 hi/lo (ms8,9), 4=dWhh0 hi (ms10)
    // streamed: ms11=dWhh0 lo, ms12/13=dWih0 hi/lo
    {
        const uint4* s = (const uint4*)(d_wpk + 6 * 8192);
        uint4* d = (uint4*)sBW;
        for (int i = tid; i < 10240; i += RT) d[i] = s[i];
    }
    float4 db0, db1;
    db0.x = decbih[uA]       + decbhh[uA];
    db0.y = decbih[64 + uA]  + decbhh[64 + uA];
    db0.z = decbih[128 + uA] + decbhh[128 + uA];
    db0.w = decbih[192 + uA] + decbhh[192 + uA];
    db1.x = decbih[256 + uA]       + decbhh[256 + uA];
    db1.y = decbih[256 + 64 + uA]  + decbhh[256 + 64 + uA];
    db1.z = decbih[256 + 128 + uA] + decbhh[256 + 128 + uA];
    db1.w = decbih[256 + 192 + uA] + decbhh[256 + 192 + uA];
    c0A = c1A = c0B = c1B = 0.f;      // c reset; h carries over
    __syncthreads();

    // -------------------- decoder: 48 steps --------------------
    for (int t = 0; t < HOR_; t++) {
        // ==== M0: dWhh0 x h0 + dWih0(gmem) x h1 ====
        {
            float Ca[4] = {0,0,0,0}, Cb[4] = {0,0,0,0};
#pragma unroll
            for (int kt = 0; kt < 4; kt++) {
                int fb = kt * 2048 + fb0;
                unsigned a0h[4], a0l[4], a1h[4], a1l[4];
                ldm4(a0h, h0hi_s + kt * 32);
                ldm4(a0l, h0lo_s + kt * 32);
                ldm4(a1h, h1hi_s + kt * 32);
                ldm4(a1l, h1lo_s + kt * 32);
                uint2 b;
                b = *(const uint2*)&sBW[4 * 8192 + fb];
                mma8(Ca, a0h, b); mma8(Ca, a0l, b);
                uint2 g = __ldg((const uint2*)&d_wpk[11 * 8192 + fb]);
                mma8(Ca, a0h, g);
                g = __ldg((const uint2*)&d_wpk[12 * 8192 + fb]);
                mma8(Ca, a1h, g); mma8(Ca, a1l, g);
                g = __ldg((const uint2*)&d_wpk[13 * 8192 + fb]);
                mma8(Ca, a1h, g);
                b = *(const uint2*)&sBW[4 * 8192 + fb + 64];
                mma8(Cb, a0h, b); mma8(Cb, a0l, b);
                g = __ldg((const uint2*)&d_wpk[11 * 8192 + fb + 64]);
                mma8(Cb, a0h, g);
                g = __ldg((const uint2*)&d_wpk[12 * 8192 + fb + 64]);
                mma8(Cb, a1h, g); mma8(Cb, a1l, g);
                g = __ldg((const uint2*)&d_wpk[13 * 8192 + fb + 64]);
                mma8(Cb, a1h, g);
            }
            float* q = qL0 + grp * QSTR + w * 16 + tid4 * 2;
            *(float2*)q        = make_float2(Ca[0], Ca[1]);
            *(float2*)(q + 8)  = make_float2(Cb[0], Cb[1]);
            float* q2 = q + 8 * QSTR;
            *(float2*)q2       = make_float2(Ca[2], Ca[3]);
            *(float2*)(q2 + 8) = make_float2(Cb[2], Cb[3]);
        }
        __syncthreads();
        // ==== U0 ====
        {
            const float* qr = qL0 + rA * QSTR + uA;
            float gi = qr[0] + db0.x, gf = qr[64] + db0.y;
            float gg = qr[128] + db0.z, go = qr[192] + db0.w;
            float cn = sigf(gf) * c0A + sigf(gi) * tanh_f(gg);
            c0A = cn;
            float hn = sigf(go) * tanh_f(cn);
            __half hh = __float2half_rn(hn);
            hbuf[rA * 72 + uA] = hh;
            hbuf[1152 + rA * 72 + uA] = __float2half_rn(hn - __half2float(hh));
        }
        if (hasB) {
            const float* qr = qL0 + rB * QSTR + uA;
            float gi = qr[0] + db0.x, gf = qr[64] + db0.y;
            float gg = qr[128] + db0.z, go = qr[192] + db0.w;
            float cn = sigf(gf) * c0B + sigf(gi) * tanh_f(gg);
            c0B = cn;
            float hn = sigf(go) * tanh_f(cn);
            __half hh = __float2half_rn(hn);
            hbuf[rB * 72 + uA] = hh;
            hbuf[1152 + rB * 72 + uA] = __float2half_rn(hn - __half2float(hh));
        }
        __syncthreads();
        // ==== M1: dWih1 x h0 + dWhh1 x h1 ====
        {
            float Ca[4] = {0,0,0,0}, Cb[4] = {0,0,0,0};
#pragma unroll
            for (int kt = 0; kt < 4; kt++) {
                int fb = kt * 2048 + fb0;
                unsigned a0h[4], a0l[4], a1h[4], a1l[4];
                ldm4(a0h, h0hi_s + kt * 32);
                ldm4(a0l, h0lo_s + kt * 32);
                ldm4(a1h, h1hi_s + kt * 32);
                ldm4(a1l, h1lo_s + kt * 32);
                uint2 b;
                b = *(const uint2*)&sBW[0 * 8192 + fb];
                mma8(Ca, a0h, b); mma8(Ca, a0l, b);
                b = *(const uint2*)&sBW[1 * 8192 + fb];
                mma8(Ca, a0h, b);
                b = *(const uint2*)&sBW[2 * 8192 + fb];
                mma8(Ca, a1h, b); mma8(Ca, a1l, b);
                b = *(const uint2*)&sBW[3 * 8192 + fb];
                mma8(Ca, a1h, b);
                b = *(const uint2*)&sBW[0 * 8192 + fb + 64];
                mma8(Cb, a0h, b); mma8(Cb, a0l, b);
                b = *(const uint2*)&sBW[1 * 8192 + fb + 64];
                mma8(Cb, a0h, b);
                b = *(const uint2*)&sBW[2 * 8192 + fb + 64];
                mma8(Cb, a1h, b); mma8(Cb, a1l, b);
                b = *(const uint2*)&sBW[3 * 8192 + fb + 64];
                mma8(Cb, a1h, b);
            }
            float* q = qL1 + grp * QSTR + w * 16 + tid4 * 2;
            *(float2*)q        = make_float2(Ca[0], Ca[1]);
            *(float2*)(q + 8)  = make_float2(Cb[0], Cb[1]);
            float* q2 = q + 8 * QSTR;
            *(float2*)q2       = make_float2(Ca[2], Ca[3]);
            *(float2*)(q2 + 8) = make_float2(Cb[2], Cb[3]);
        }
        __syncthreads();
        // ==== U1 ====
        {
            const float* qr = qL1 + rA * QSTR + uA;
            float gi = qr[0] + db1.x, gf = qr[64] + db1.y;
            float gg = qr[128] + db1.z, go = qr[192] + db1.w;
            float cn = sigf(gf) * c1A + sigf(gi) * tanh_f(gg);
            c1A = cn;
            float hn = sigf(go) * tanh_f(cn);
            __half hh = __float2half_rn(hn);
            hbuf[2304 + rA * 72 + uA] = hh;
            hbuf[3456 + rA * 72 + uA] = __float2half_rn(hn - __half2float(hh));
        }
        if (hasB) {
            const float* qr = qL1 + rB * QSTR + uA;
            float gi = qr[0] + db1.x, gf = qr[64] + db1.y;
            float gg = qr[128] + db1.z, go = qr[192] + db1.w;
            float cn = sigf(gf) * c1B + sigf(gi) * tanh_f(gg);
            c1B = cn;
            float hn = sigf(go) * tanh_f(cn);
            __half hh = __float2half_rn(hn);
            hbuf[2304 + rB * 72 + uA] = hh;
            hbuf[3456 + rB * 72 + uA] = __float2half_rn(hn - __half2float(hh));
        }
        __syncthreads();
        // ==== regression head ====
        if (tid < NROW * FOUT_) {
            int r = tid >> 3, o = tid & 7;
            int b = b0 + r;
            if (b < B_) {
                float a = __ldg(&breg[o]);
#pragma unroll
                for (int k = 0; k < H_; k++) {
                    float hk = __half2float(hbuf[2304 + r * 72 + k])
                             + __half2float(hbuf[3456 + r * 72 + k]);
                    a = fmaf(hk, __ldg(&Wreg[o * H_ + k]), a);
                }
                out[((size_t)b * HOR_ + t) * FOUT_ + o] = a;
            }
        }
    }
}

// ---------------- launch ----------------
extern "C" void kernel_launch(void* const* d_in, const int* in_sizes, int n_in,
                              void* d_out, int out_size)
{
    const float* X      = (const float*)d_in[0];
    // d_in[1] = X_mask : all-ones, unused by reference
    const float* W_emb  = (const float*)d_in[2];
    const float* b_emb  = (const float*)d_in[3];
    const float* encWih = (const float*)d_in[4];
    const float* encWhh = (const float*)d_in[5];
    const float* encbih = (const float*)d_in[6];
    const float* encbhh = (const float*)d_in[7];
    const float* decWih = (const float*)d_in[8];
    const float* decWhh = (const float*)d_in[9];
    const float* decbih = (const float*)d_in[10];
    const float* decbhh = (const float*)d_in[11];
    const float* W_reg  = (const float*)d_in[12];
    const float* b_reg  = (const float*)d_in[13];
    float* out = (float*)d_out;

    cudaFuncSetAttribute(rnn_kernel, cudaFuncAttributeMaxDynamicSharedMemorySize, SMEM_BYTES);

    prep_kernel<<<FIN_ + 1, 256>>>(W_emb, b_emb, encWih, encbih, encbhh);
    pack_kernel<<<14, 256>>>(encWih, encWhh, decWih, decWhh);
    emb_gemm<<<dim3(B_ / 128, T_), 256>>>(X);
    rnn_kernel<<<NCTA, RT, SMEM_BYTES>>>(encbih, encbhh, decbih, decbhh,
                                         W_reg, b_reg, out);
}

// round 17
// speedup vs baseline: 2.7237x; 1.0596x over previous
#include <cuda_runtime.h>
#include <cuda_fp16.h>

// Problem constants
#define B_    2048
#define T_    512
#define FIN_  32
#define H_    64
#define G4_   256        // 4*H
#define HOR_  48
#define FOUT_ 8
#define NROW  14         // batch rows per CTA (padded to 16 for MMA)
#define NCTA  147
#define RT    512
#define G0ROW (B_ * G4_)

// ---------------- scratch (__device__ globals; no cudaMalloc allowed) ----------------
// d_g0 layout: [t][b][unit*4 + gate]  (float4 per hidden unit = {i,f,g,o})
__device__ float d_g0[(size_t)T_ * B_ * G4_];
__device__ float d_WcT[FIN_ * G4_];      // combined (Wih0 @ W_emb), pidx channel order
__device__ float d_bc[G4_];              // combined layer0 bias, pidx order
// fragment-major fp16 packed weights: 7 matrices x {hi,lo} x 8192 u32
// ms ids: 0/1=eWih1 2/3=eWhh1 4/5=eWhh0 6/7=dWih1 8/9=dWhh1 10/11=dWhh0 12/13=dWih0
__device__ unsigned d_wpk[14 * 8192];

// ---------------- fast activations ----------------
__device__ __forceinline__ float sigf(float x) {
    return __fdividef(1.0f, 1.0f + __expf(-x));
}
__device__ __forceinline__ float tanh_f(float x) {
    return __fdividef(2.0f, 1.0f + __expf(-2.0f * x)) - 1.0f;
}
// one LSTM cell update; returns h
__device__ __forceinline__ float cell_upd(float gi, float gf, float gg, float go, float& c) {
    float cn = sigf(gf) * c + sigf(gi) * tanh_f(gg);
    c = cn;
    return sigf(go) * tanh_f(cn);
}

// packed output-channel index: gate g (0..255) -> unit*4 + gate_slot (x-part layout)
__device__ __forceinline__ int pidx(int g) { return ((g & 63) << 2) + (g >> 6); }

// ---------------- mma / ldmatrix helpers ----------------
__device__ __forceinline__ void mma8(float c[4], const unsigned a[4], uint2 b) {
    asm volatile("mma.sync.aligned.m16n8k16.row.col.f32.f16.f16.f32 "
        "{%0,%1,%2,%3}, {%4,%5,%6,%7}, {%8,%9}, {%0,%1,%2,%3};"
        : "+f"(c[0]), "+f"(c[1]), "+f"(c[2]), "+f"(c[3])
        : "r"(a[0]), "r"(a[1]), "r"(a[2]), "r"(a[3]), "r"(b.x), "r"(b.y));
}
__device__ __forceinline__ void ldm4(unsigned a[4], unsigned saddr) {
    asm volatile("ldmatrix.sync.aligned.m8n8.x4.shared.b16 {%0,%1,%2,%3}, [%4];"
        : "=r"(a[0]), "=r"(a[1]), "=r"(a[2]), "=r"(a[3]) : "r"(saddr));
}

// ---------------- prep: combined layer0 input weights / bias ----------------
__global__ void prep_kernel(const float* __restrict__ W_emb, const float* __restrict__ b_emb,
                            const float* __restrict__ encWih, const float* __restrict__ encbih,
                            const float* __restrict__ encbhh)
{
    int g  = threadIdx.x;
    int bb = blockIdx.x;
    float wrow[H_];
#pragma unroll
    for (int h = 0; h < H_; h++) wrow[h] = encWih[g * H_ + h];

    if (bb == FIN_) {
        float b = encbih[g] + encbhh[g];
#pragma unroll
        for (int h = 0; h < H_; h++) b = fmaf(wrow[h], b_emb[h], b);
        d_bc[pidx(g)] = b;
    } else {
        int f = bb;
        float s = 0.f;
#pragma unroll
        for (int h = 0; h < H_; h++) s = fmaf(wrow[h], W_emb[h * FIN_ + f], s);
        d_WcT[f * G4_ + pidx(g)] = s;
    }
}

// ---------------- pack: fragment-major fp16 hi/lo weights, gate-grouped columns ----
// B column mapping: warp w = nt>>1 owns units 4w..4w+3.
// tile (nt even) columns = {i,f} of units; tile (nt odd) = {g,o}.
// column c (=l>>2): unit = 4*(nt>>1) + (c>>1), slot = 2*(nt&1) + (c&1), gate = slot*64+unit.
__global__ void pack_kernel(const float* __restrict__ encWih, const float* __restrict__ encWhh,
                            const float* __restrict__ decWih, const float* __restrict__ decWhh)
{
    int ms = blockIdx.x;           // 0..13
    int m = ms >> 1, s = ms & 1;
    const float* src;
    switch (m) {
        case 0: src = encWih + 16384; break;
        case 1: src = encWhh + 16384; break;
        case 2: src = encWhh;         break;
        case 3: src = decWih + 16384; break;
        case 4: src = decWhh + 16384; break;
        case 5: src = decWhh;         break;
        default: src = decWih;        break;   // dWih0
    }
    for (int i = threadIdx.x; i < 8192; i += 256) {
        int kt = i >> 11, nt = (i >> 6) & 31, l = (i >> 1) & 31, j = i & 1;
        int k = kt * 16 + (l & 3) * 2 + j * 8;
        int c = l >> 2;
        int unit = 4 * (nt >> 1) + (c >> 1);
        int slot = 2 * (nt & 1) + (c & 1);
        int n = slot * 64 + unit;
        float v0 = src[n * 64 + k], v1 = src[n * 64 + k + 1];
        __half h0 = __float2half_rn(v0), h1 = __float2half_rn(v1);
        __half2 o;
        if (s == 0) o = __halves2half2(h0, h1);
        else o = __halves2half2(__float2half_rn(v0 - __half2float(h0)),
                                __float2half_rn(v1 - __half2float(h1)));
        d_wpk[ms * 8192 + i] = *(unsigned*)&o;
    }
}

// ---------------- GEMM: d_g0[t][b][c] = X[b][t][:] @ WcT[:, c] + bc[c] ----------------
__global__ void __launch_bounds__(256)
emb_gemm(const float* __restrict__ X)
{
    __shared__ float sX[128 * FIN_];
    const int t   = blockIdx.y;
    const int b0  = blockIdx.x * 128;
    const int tid = threadIdx.x;

#pragma unroll
    for (int q = 0; q < 4; q++) {
        int lin = tid + q * 256;
        int rr = lin >> 3, f4 = lin & 7;
        float4 v = *(const float4*)(X + ((size_t)(b0 + rr) * T_ + t) * FIN_ + f4 * 4);
        *(float4*)(sX + rr * FIN_ + f4 * 4) = v;
    }
    float w[FIN_];
#pragma unroll
    for (int f = 0; f < FIN_; f++) w[f] = d_WcT[f * G4_ + tid];
    const float bias = d_bc[tid];
    __syncthreads();

    float* dst = d_g0 + (size_t)t * B_ * G4_ + (size_t)b0 * G4_ + tid;
#pragma unroll 2
    for (int rr = 0; rr < 128; rr++) {
        float a = bias;
        const float* xr = sX + rr * FIN_;
#pragma unroll
        for (int f = 0; f < FIN_; f += 4) {
            float4 x = *(const float4*)(xr + f);
            a = fmaf(x.x, w[f + 0], a);
            a = fmaf(x.y, w[f + 1], a);
            a = fmaf(x.z, w[f + 2], a);
            a = fmaf(x.w, w[f + 3], a);
        }
        dst[(size_t)rr * G4_] = a;
    }
}

// smem: sBW 5*32768B | hbuf 2 buffers x 4 x [16][72] half = 18432B
#define HOFF 163840
#define SMEM_BYTES (HOFF + 18432)

__global__ void __launch_bounds__(RT, 1)
rnn_kernel(const float* __restrict__ encbih, const float* __restrict__ encbhh,
           const float* __restrict__ decbih, const float* __restrict__ decbhh,
           const float* __restrict__ Wreg,   const float* __restrict__ breg,
           float* __restrict__ out)
{
    extern __shared__ char smc[];
    unsigned* sBW = (unsigned*)smc;                 // 5 buffers x 8192 u32
    __half* hbuf  = (__half*)(smc + HOFF);          // 2 buffers x 4608 halfs
    // within a buffer: h0hi @0, h0lo @1152, h1hi @2304, h1lo @3456 (halfs)

    const int tid  = threadIdx.x;
    const int w    = tid >> 5, l = tid & 31;
    const int b0   = blockIdx.x * NROW;
    const int unit = 4 * w + (l & 3);       // this thread's hidden unit
    const int rA   = l >> 2;                // rows rA and rA+8
    const int rC   = rA + 8;
    const int oA   = rA * 72 + unit;
    const int oC   = rC * 72 + unit;

    // ---- copy encoder weights: ms0..4 ----
    {
        const uint4* s = (const uint4*)d_wpk;
        uint4* d = (uint4*)sBW;
        for (int i = tid; i < 10240; i += RT) d[i] = s[i];
    }
    for (int i = tid; i < 4608; i += RT) ((unsigned*)hbuf)[i] = 0u;

    // ldmatrix per-lane base address (buffer 0)
    const unsigned sb = (unsigned)__cvta_generic_to_shared(smc);
    const unsigned habase = sb + HOFF + (((l & 15) * 72 + ((l >> 1) & 8)) << 1);
    const int fb0 = (2 * w) * 64 + l * 2;

    // biases for this unit
    float4 eb1;
    eb1.x = encbih[256 + unit]       + encbhh[256 + unit];
    eb1.y = encbih[256 + 64 + unit]  + encbhh[256 + 64 + unit];
    eb1.z = encbih[256 + 128 + unit] + encbhh[256 + 128 + unit];
    eb1.w = encbih[256 + 192 + unit] + encbhh[256 + 192 + unit];

    // x-part gmem offsets (clamped for padding/tail rows)
    int bA = b0 + rA; if (bA >= B_) bA = B_ - 1;
    int bC = b0 + rC; if (bC >= B_) bC = B_ - 1;
    const size_t gxoA = (size_t)bA * G4_ + (unit << 2);
    const size_t gxoC = (size_t)bC * G4_ + (unit << 2);

    float4 gxA = *(const float4*)(d_g0 + gxoA);           // x(0)
    float4 gxC = *(const float4*)(d_g0 + gxoC);
    float c0A = 0.f, c0C = 0.f, c1A = 0.f, c1C = 0.f;
    float h0A_f = 0.f, h0C_f = 0.f;
    __syncthreads();

    // ---- prologue: h0(0) = lstm(x(0)) into buffer 0 ----
    {
        float h = cell_upd(gxA.x, gxA.y, gxA.z, gxA.w, c0A);
        h0A_f = h;
        __half hh = __float2half_rn(h);
        hbuf[oA] = hh; hbuf[1152 + oA] = __float2half_rn(h - __half2float(hh));
        h = cell_upd(gxC.x, gxC.y, gxC.z, gxC.w, c0C);
        h0C_f = h;
        hh = __float2half_rn(h);
        hbuf[oC] = hh; hbuf[1152 + oC] = __float2half_rn(h - __half2float(hh));
    }
    gxA = *(const float4*)(d_g0 + (size_t)1 * G0ROW + gxoA);   // x(1)
    gxC = *(const float4*)(d_g0 + (size_t)1 * G0ROW + gxoC);
    __syncthreads();

    // -------------------- encoder fused supersteps s = 0..510 --------------------
    // read buf (s&1): h0(s), h1(s-1) ; write buf ^1: h1(s), h0(s+1). ONE barrier/step.
    for (int s = 0; s < T_ - 1; s++) {
        const int p = s & 1;
        const unsigned rb = habase + p * 9216;
        __half* wb = hbuf + ((p ^ 1) * 4608);
        float C1a[4] = {0,0,0,0}, C1b[4] = {0,0,0,0};
        float C0a[4] = {0,0,0,0}, C0b[4] = {0,0,0,0};
#pragma unroll
        for (int kt = 0; kt < 4; kt++) {
            int fb = kt * 2048 + fb0;
            unsigned a0h[4], a0l[4];
            ldm4(a0h, rb + kt * 32);
            ldm4(a0l, rb + 2304 + kt * 32);
            uint2 b;
            b = *(const uint2*)&sBW[0 * 8192 + fb];      mma8(C1a, a0h, b); mma8(C1a, a0l, b);
            b = *(const uint2*)&sBW[1 * 8192 + fb];      mma8(C1a, a0h, b);
            b = *(const uint2*)&sBW[0 * 8192 + fb + 64]; mma8(C1b, a0h, b); mma8(C1b, a0l, b);
            b = *(const uint2*)&sBW[1 * 8192 + fb + 64]; mma8(C1b, a0h, b);
            b = *(const uint2*)&sBW[4 * 8192 + fb];      mma8(C0a, a0h, b); mma8(C0a, a0l, b);
            uint2 g5 = __ldg((const uint2*)&d_wpk[5 * 8192 + fb]);
            mma8(C0a, a0h, g5);
            b = *(const uint2*)&sBW[4 * 8192 + fb + 64]; mma8(C0b, a0h, b); mma8(C0b, a0l, b);
            g5 = __ldg((const uint2*)&d_wpk[5 * 8192 + fb + 64]);
            mma8(C0b, a0h, g5);
            unsigned a1h[4], a1l[4];
            ldm4(a1h, rb + 4608 + kt * 32);
            ldm4(a1l, rb + 6912 + kt * 32);
            b = *(const uint2*)&sBW[2 * 8192 + fb];      mma8(C1a, a1h, b); mma8(C1a, a1l, b);
            b = *(const uint2*)&sBW[3 * 8192 + fb];      mma8(C1a, a1h, b);
            b = *(const uint2*)&sBW[2 * 8192 + fb + 64]; mma8(C1b, a1h, b); mma8(C1b, a1l, b);
            b = *(const uint2*)&sBW[3 * 8192 + fb + 64]; mma8(C1b, a1h, b);
        }
        // ---- in-register LSTM updates ----
        {
            float h = cell_upd(C1a[0] + eb1.x, C1a[1] + eb1.y, C1b[0] + eb1.z, C1b[1] + eb1.w, c1A);
            __half hh = __float2half_rn(h);
            wb[2304 + oA] = hh; wb[3456 + oA] = __float2half_rn(h - __half2float(hh));
            h = cell_upd(C1a[2] + eb1.x, C1a[3] + eb1.y, C1b[2] + eb1.z, C1b[3] + eb1.w, c1C);
            hh = __float2half_rn(h);
            wb[2304 + oC] = hh; wb[3456 + oC] = __float2half_rn(h - __half2float(hh));
            h = cell_upd(C0a[0] + gxA.x, C0a[1] + gxA.y, C0b[0] + gxA.z, C0b[1] + gxA.w, c0A);
            h0A_f = h;
            hh = __float2half_rn(h);
            wb[oA] = hh; wb[1152 + oA] = __float2half_rn(h - __half2float(hh));
            h = cell_upd(C0a[2] + gxC.x, C0a[3] + gxC.y, C0b[2] + gxC.z, C0b[3] + gxC.w, c0C);
            h0C_f = h;
            hh = __float2half_rn(h);
            wb[oC] = hh; wb[1152 + oC] = __float2half_rn(h - __half2float(hh));
        }
        if (s + 2 < T_) {   // prefetch x(s+2)
            gxA = *(const float4*)(d_g0 + (size_t)(s + 2) * G0ROW + gxoA);
            gxC = *(const float4*)(d_g0 + (size_t)(s + 2) * G0ROW + gxoC);
        }
        __syncthreads();
    }

    // ---- epilogue: h1(511) from buf1 (h0(511), h1(510)); write full state to buf0 ----
    {
        const unsigned rb = habase + 9216;
        __half* wb = hbuf;   // buffer 0
        float C1a[4] = {0,0,0,0}, C1b[4] = {0,0,0,0};
#pragma unroll
        for (int kt = 0; kt < 4; kt++) {
            int fb = kt * 2048 + fb0;
            unsigned a0h[4], a0l[4], a1h[4], a1l[4];
            ldm4(a0h, rb + kt * 32);
            ldm4(a0l, rb + 2304 + kt * 32);
            ldm4(a1h, rb + 4608 + kt * 32);
            ldm4(a1l, rb + 6912 + kt * 32);
            uint2 b;
            b = *(const uint2*)&sBW[0 * 8192 + fb];      mma8(C1a, a0h, b); mma8(C1a, a0l, b);
            b = *(const uint2*)&sBW[1 * 8192 + fb];      mma8(C1a, a0h, b);
            b = *(const uint2*)&sBW[2 * 8192 + fb];      mma8(C1a, a1h, b); mma8(C1a, a1l, b);
            b = *(const uint2*)&sBW[3 * 8192 + fb];      mma8(C1a, a1h, b);
            b = *(const uint2*)&sBW[0 * 8192 + fb + 64]; mma8(C1b, a0h, b); mma8(C1b, a0l, b);
            b = *(const uint2*)&sBW[1 * 8192 + fb + 64]; mma8(C1b, a0h, b);
            b = *(const uint2*)&sBW[2 * 8192 + fb + 64]; mma8(C1b, a1h, b); mma8(C1b, a1l, b);
            b = *(const uint2*)&sBW[3 * 8192 + fb + 64]; mma8(C1b, a1h, b);
        }
        float h = cell_upd(C1a[0] + eb1.x, C1a[1] + eb1.y, C1b[0] + eb1.z, C1b[1] + eb1.w, c1A);
        __half hh = __float2half_rn(h);
        wb[2304 + oA] = hh; wb[3456 + oA] = __float2half_rn(h - __half2float(hh));
        h = cell_upd(C1a[2] + eb1.x, C1a[3] + eb1.y, C1b[2] + eb1.z, C1b[3] + eb1.w, c1C);
        hh = __float2half_rn(h);
        wb[2304 + oC] = hh; wb[3456 + oC] = __float2half_rn(h - __half2float(hh));
        // h0(511) from saved registers
        hh = __float2half_rn(h0A_f);
        wb[oA] = hh; wb[1152 + oA] = __float2half_rn(h0A_f - __half2float(hh));
        hh = __float2half_rn(h0C_f);
        wb[oC] = hh; wb[1152 + oC] = __float2half_rn(h0C_f - __half2float(hh));
    }
    __syncthreads();

    // -------------------- decoder setup --------------------
    // smem bufs: 0/1=dWih1 hi/lo, 2/3=dWhh1 hi/lo, 4=dWhh0 hi
    // streamed: ms11=dWhh0 lo, ms12/13=dWih0 hi/lo
    {
        const uint4* s = (const uint4*)(d_wpk + 6 * 8192);
        uint4* d = (uint4*)sBW;
        for (int i = tid; i < 10240; i += RT) d[i] = s[i];
    }
    float4 db0, db1;
    db0.x = decbih[unit]       + decbhh[unit];
    db0.y = decbih[64 + unit]  + decbhh[64 + unit];
    db0.z = decbih[128 + unit] + decbhh[128 + unit];
    db0.w = decbih[192 + unit] + decbhh[192 + unit];
    db1.x = decbih[256 + unit]       + decbhh[256 + unit];
    db1.y = decbih[256 + 64 + unit]  + decbhh[256 + 64 + unit];
    db1.z = decbih[256 + 128 + unit] + decbhh[256 + 128 + unit];
    db1.w = decbih[256 + 192 + unit] + decbhh[256 + 192 + unit];
    c0A = c0C = c1A = c1C = 0.f;      // c reset; h carries over in buffer 0
    __syncthreads();

    // -------------------- decoder: 48 steps --------------------
    int p = 0;
    for (int t = 0; t < HOR_; t++) {
        const unsigned rb = habase + p * 9216;        // h0(t-1), h1(t-1)
        const unsigned rq = habase + (p ^ 1) * 9216;  // h0(t) after U0
        __half* wb = hbuf + ((p ^ 1) * 4608);
        // ==== M0: dWhh0 x h0 + dWih0(gmem) x h1 ====
        {
            float Ca[4] = {0,0,0,0}, Cb[4] = {0,0,0,0};
#pragma unroll
            for (int kt = 0; kt < 4; kt++) {
                int fb = kt * 2048 + fb0;
                unsigned a0h[4], a0l[4], a1h[4], a1l[4];
                ldm4(a0h, rb + kt * 32);
                ldm4(a0l, rb + 2304 + kt * 32);
                ldm4(a1h, rb + 4608 + kt * 32);
                ldm4(a1l, rb + 6912 + kt * 32);
                uint2 b, g;
                b = *(const uint2*)&sBW[4 * 8192 + fb];      mma8(Ca, a0h, b); mma8(Ca, a0l, b);
                g = __ldg((const uint2*)&d_wpk[11 * 8192 + fb]);      mma8(Ca, a0h, g);
                g = __ldg((const uint2*)&d_wpk[12 * 8192 + fb]);      mma8(Ca, a1h, g); mma8(Ca, a1l, g);
                g = __ldg((const uint2*)&d_wpk[13 * 8192 + fb]);      mma8(Ca, a1h, g);
                b = *(const uint2*)&sBW[4 * 8192 + fb + 64]; mma8(Cb, a0h, b); mma8(Cb, a0l, b);
                g = __ldg((const uint2*)&d_wpk[11 * 8192 + fb + 64]); mma8(Cb, a0h, g);
                g = __ldg((const uint2*)&d_wpk[12 * 8192 + fb + 64]); mma8(Cb, a1h, g); mma8(Cb, a1l, g);
                g = __ldg((const uint2*)&d_wpk[13 * 8192 + fb + 64]); mma8(Cb, a1h, g);
            }
            float h = cell_upd(Ca[0] + db0.x, Ca[1] + db0.y, Cb[0] + db0.z, Cb[1] + db0.w, c0A);
            __half hh = __float2half_rn(h);
            wb[oA] = hh; wb[1152 + oA] = __float2half_rn(h - __half2float(hh));
            h = cell_upd(Ca[2] + db0.x, Ca[3] + db0.y, Cb[2] + db0.z, Cb[3] + db0.w, c0C);
            hh = __float2half_rn(h);
            wb[oC] = hh; wb[1152 + oC] = __float2half_rn(h - __half2float(hh));
        }
        __syncthreads();
        // ==== M1: dWih1 x h0(t) [buf q] + dWhh1 x h1(t-1) [buf p] ====
        {
            float Ca[4] = {0,0,0,0}, Cb[4] = {0,0,0,0};
#pragma unroll
            for (int kt = 0; kt < 4; kt++) {
                int fb = kt * 2048 + fb0;
                unsigned a0h[4], a0l[4], a1h[4], a1l[4];
                ldm4(a0h, rq + kt * 32);
                ldm4(a0l, rq + 2304 + kt * 32);
                ldm4(a1h, rb + 4608 + kt * 32);
                ldm4(a1l, rb + 6912 + kt * 32);
                uint2 b;
                b = *(const uint2*)&sBW[0 * 8192 + fb];      mma8(Ca, a0h, b); mma8(Ca, a0l, b);
                b = *(const uint2*)&sBW[1 * 8192 + fb];      mma8(Ca, a0h, b);
                b = *(const uint2*)&sBW[2 * 8192 + fb];      mma8(Ca, a1h, b); mma8(Ca, a1l, b);
                b = *(const uint2*)&sBW[3 * 8192 + fb];      mma8(Ca, a1h, b);
                b = *(const uint2*)&sBW[0 * 8192 + fb + 64]; mma8(Cb, a0h, b); mma8(Cb, a0l, b);
                b = *(const uint2*)&sBW[1 * 8192 + fb + 64]; mma8(Cb, a0h, b);
                b = *(const uint2*)&sBW[2 * 8192 + fb + 64]; mma8(Cb, a1h, b); mma8(Cb, a1l, b);
                b = *(const uint2*)&sBW[3 * 8192 + fb + 64]; mma8(Cb, a1h, b);
            }
            float h = cell_upd(Ca[0] + db1.x, Ca[1] + db1.y, Cb[0] + db1.z, Cb[1] + db1.w, c1A);
            __half hh = __float2half_rn(h);
            wb[2304 + oA] = hh; wb[3456 + oA] = __float2half_rn(h - __half2float(hh));
            h = cell_upd(Ca[2] + db1.x, Ca[3] + db1.y, Cb[2] + db1.z, Cb[3] + db1.w, c1C);
            hh = __float2half_rn(h);
            wb[2304 + oC] = hh; wb[3456 + oC] = __float2half_rn(h - __half2float(hh));
        }
        __syncthreads();
        // ==== regression head: y = h1(t) @ Wreg^T + breg (buf q) ====
        if (tid < NROW * FOUT_) {
            int r = tid >> 3, o = tid & 7;
            int b = b0 + r;
            if (b < B_) {
                const __half* h1b = hbuf + (p ^ 1) * 4608 + 2304 + r * 72;
                float a = __ldg(&breg[o]);
#pragma unroll
                for (int k = 0; k < H_; k++) {
                    float hk = __half2float(h1b[k]) + __half2float(h1b[1152 + k]);
                    a = fmaf(hk, __ldg(&Wreg[o * H_ + k]), a);
                }
                out[((size_t)b * HOR_ + t) * FOUT_ + o] = a;
            }
        }
        p ^= 1;
    }
}

// ---------------- launch ----------------
extern "C" void kernel_launch(void* const* d_in, const int* in_sizes, int n_in,
                              void* d_out, int out_size)
{
    const float* X      = (const float*)d_in[0];
    // d_in[1] = X_mask : all-ones, unused by reference
    const float* W_emb  = (const float*)d_in[2];
    const float* b_emb  = (const float*)d_in[3];
    const float* encWih = (const float*)d_in[4];
    const float* encWhh = (const float*)d_in[5];
    const float* encbih = (const float*)d_in[6];
    const float* encbhh = (const float*)d_in[7];
    const float* decWih = (const float*)d_in[8];
    const float* decWhh = (const float*)d_in[9];
    const float* decbih = (const float*)d_in[10];
    const float* decbhh = (const float*)d_in[11];
    const float* W_reg  = (const float*)d_in[12];
    const float* b_reg  = (const float*)d_in[13];
    float* out = (float*)d_out;

    cudaFuncSetAttribute(rnn_kernel, cudaFuncAttributeMaxDynamicSharedMemorySize, SMEM_BYTES);

    prep_kernel<<<FIN_ + 1, 256>>>(W_emb, b_emb, encWih, encbih, encbhh);
    pack_kernel<<<14, 256>>>(encWih, encWhh, decWih, decWhh);
    emb_gemm<<<dim3(B_ / 128, T_), 256>>>(X);
    rnn_kernel<<<NCTA, RT, SMEM_BYTES>>>(encbih, encbhh, decbih, decbhh,
                                         W_reg, b_reg, out);
}